// round 4
// baseline (speedup 1.0000x reference)
#include <cuda_runtime.h>
#include <math.h>
#include <stdint.h>

// ---------------- dims ----------------
static const int Lc = 12, Hc = 12, Dc = 768, HDc = 64, Mc = 3072;
static const int IMGc = 384, Bc = 32, NCc = 1000;
static const int NP = 576;
static const int Sc = 577;
static const int BS = Bc * Sc;        // 18464
static const int GRID24 = 24;
static const int KTW = 640;
static const int GS = 4;              // gemm pipeline stages

// ---------------- scratch ----------------
__device__ float g_t[BS * Dc];
__device__ float g_h[BS * Dc];
__device__ float g_om[BS * Dc];
__device__ float g_qkv[BS * 3 * Dc];
__device__ float g_mbuf[BS * Mc];
__device__ float g_col[Bc * NP * Dc];
__device__ float g_wtqkv[Lc * Dc * 3 * Dc];
__device__ float g_cwt[Dc * Dc];
__device__ float g_cls[Bc * Dc];
__device__ float g_kT[(long long)Bc * Hc * HDc * KTW];
__device__ float g_wmsar[Lc * Dc * Dc];
__device__ float g_w1r[Lc * Dc * Mc];
__device__ float g_w2r[Lc * Mc * Dc];
__device__ float g_whr[Dc * NCc];

// ---------------- tf32 helpers ----------------
__device__ __forceinline__ uint32_t f2tf(float f) {
    uint32_t u;
    asm("cvt.rna.tf32.f32 %0, %1;" : "=r"(u) : "f"(f));
    return u;
}
__device__ __forceinline__ float f2tf_f(float f) { return __uint_as_float(f2tf(f)); }

__device__ __forceinline__ void mma_tf32(float c[4], const uint32_t a[4], const uint32_t b[2]) {
    asm volatile(
        "mma.sync.aligned.m16n8k8.row.col.f32.tf32.tf32.f32 "
        "{%0,%1,%2,%3}, {%4,%5,%6,%7}, {%8,%9}, {%0,%1,%2,%3};\n"
        : "+f"(c[0]), "+f"(c[1]), "+f"(c[2]), "+f"(c[3])
        : "r"(a[0]), "r"(a[1]), "r"(a[2]), "r"(a[3]), "r"(b[0]), "r"(b[1]));
}

__device__ __forceinline__ void cp_async16(void* smem_dst, const void* gsrc, int sz) {
    unsigned sm = (unsigned)__cvta_generic_to_shared(smem_dst);
    asm volatile("cp.async.ca.shared.global [%0], [%1], 16, %2;\n" :: "r"(sm), "l"(gsrc), "r"(sz));
}

// ---------------- dense tf32 GEMM, 4-warp 64x64 warp tile, 4-stage pipeline ----------------
// C[M,N] = act( A@B + bias + res );  inputs pre-rounded tf32; optional tf32 round on out.
// dynamic smem: As[GS][128][20] then Bs[GS][16][136]
__global__ void __launch_bounds__(128)
mma_gemm_kernel(const float* __restrict__ A, const float* __restrict__ Bm,
                const float* __restrict__ bias, const float* __restrict__ res,
                float* __restrict__ C,
                int M, int N, int K, int lda, int ldb, int ldc,
                int act, int rnd) {
    extern __shared__ float sm[];
    float* As = sm;                   // GS * 2560
    float* Bs = sm + GS * 2560;       // GS * 2176

    int t = threadIdx.x;
    int lane = t & 31, wid = t >> 5;
    int wm = wid >> 1, wn = wid & 1;          // 2x2 warps
    int g = lane >> 2, tig = lane & 3;
    int m0 = blockIdx.y * 128, n0 = blockIdx.x * 128;

    float acc[4][8][4] = {};
    int nk = K / 16;                           // K always multiple of 16, nk >= GS-1

    auto loadA = [&](int k0, int s) {
        float* dst = As + s * 2560;
#pragma unroll
        for (int i = 0; i < 4; i++) {
            int c = t + i * 128;
            int m = c >> 2, kq = (c & 3) * 4;
            const float* src = A + (long long)(m0 + m) * lda + k0 + kq;
            cp_async16(dst + m * 20 + kq, src, (m0 + m < M) ? 16 : 0);
        }
    };
    auto loadB = [&](int k0, int s) {
        float* dst = Bs + s * 2176;
#pragma unroll
        for (int i = 0; i < 4; i++) {
            int c = t + i * 128;
            int k = c >> 5, nq = (c & 31) * 4;
            const float* src = Bm + (long long)(k0 + k) * ldb + n0 + nq;
            cp_async16(dst + k * 136 + nq, src, (n0 + nq < N) ? 16 : 0);
        }
    };

    // prologue: stages 0..GS-2
#pragma unroll
    for (int s = 0; s < GS - 1; s++) {
        loadA(s * 16, s);
        loadB(s * 16, s);
        asm volatile("cp.async.commit_group;\n");
    }

    for (int it = 0; it < nk; it++) {
        asm volatile("cp.async.wait_group %0;\n" :: "n"(GS - 2));
        __syncthreads();
        // issue stage it+GS-1 (overwrites stage (it-1)%GS, freed by the sync above)
        if (it + GS - 1 < nk) {
            int s = (it + GS - 1) % GS;
            loadA((it + GS - 1) * 16, s);
            loadB((it + GS - 1) * 16, s);
        }
        asm volatile("cp.async.commit_group;\n");   // always commit (keeps count invariant)

        int s = it % GS;
        const float* Ab = As + s * 2560;
        const float* Bb = Bs + s * 2176;
#pragma unroll
        for (int ks = 0; ks < 2; ks++) {
            int kk = ks * 8;
            uint32_t af[4][4], bf[8][2];
#pragma unroll
            for (int mt = 0; mt < 4; mt++) {
                int mr = wm * 64 + mt * 16 + g;
                af[mt][0] = __float_as_uint(Ab[mr * 20 + kk + tig]);
                af[mt][1] = __float_as_uint(Ab[(mr + 8) * 20 + kk + tig]);
                af[mt][2] = __float_as_uint(Ab[mr * 20 + kk + tig + 4]);
                af[mt][3] = __float_as_uint(Ab[(mr + 8) * 20 + kk + tig + 4]);
            }
#pragma unroll
            for (int nf = 0; nf < 8; nf++) {
                int nc = wn * 64 + nf * 8 + g;
                bf[nf][0] = __float_as_uint(Bb[(kk + tig) * 136 + nc]);
                bf[nf][1] = __float_as_uint(Bb[(kk + tig + 4) * 136 + nc]);
            }
#pragma unroll
            for (int mt = 0; mt < 4; mt++)
#pragma unroll
                for (int nf = 0; nf < 8; nf++)
                    mma_tf32(acc[mt][nf], af[mt], bf[nf]);
        }
    }

    // epilogue
#pragma unroll
    for (int mt = 0; mt < 4; mt++) {
#pragma unroll
        for (int nf = 0; nf < 8; nf++) {
            int row = m0 + wm * 64 + mt * 16 + g;
            int col = n0 + wn * 64 + nf * 8 + tig * 2;
#pragma unroll
            for (int cc = 0; cc < 4; cc++) {
                int m = row + (cc >> 1) * 8;
                int n = col + (cc & 1);
                if (m >= M || n >= N) continue;
                float v = acc[mt][nf][cc];
                if (bias) v += bias[n];
                if (res) v += res[(long long)m * ldc + n];
                if (act == 1) v = 0.5f * v * (1.0f + erff(v * 0.7071067811865476f));
                if (rnd) v = f2tf_f(v);
                C[(long long)m * ldc + n] = v;
            }
        }
    }
}

// ---------------- fused flash attention (unchanged from R3) ----------------
__global__ void __launch_bounds__(256)
flash_kernel(const float* __restrict__ qkv, const float* __restrict__ kT,
             float* __restrict__ om) {
    extern __shared__ float smf[];
    float* Qs = smf;               // [128][68]
    float* Ps = smf + 8704;        // [8][16][68]
    float* Ks = smf + 17408;       // [2][64][72]
    float* Vs = smf + 26624;       // [2][64][72]

    int qt = blockIdx.x, h = blockIdx.y, b = blockIdx.z;
    int t = threadIdx.x, lane = t & 31, w = t >> 5, g = lane >> 2, tig = lane & 3;
    const float* qb = qkv + (long long)b * Sc * 2304 + h * 192;
    const float* kb = kT + ((long long)(b * Hc + h)) * HDc * KTW;

#pragma unroll
    for (int i = 0; i < 8; i++) {
        int idx = t + i * 256;
        int row = idx >> 4, c4 = (idx & 15) * 4;
        int gr = qt * 128 + row;
        cp_async16(&Qs[row * 68 + c4], qb + (long long)gr * 2304 + c4, gr < Sc ? 16 : 0);
    }
    auto issueK = [&](int kt_, int buf) {
#pragma unroll
        for (int i = 0; i < 4; i++) {
            int idx = t + i * 256;
            int hd = idx >> 4, c4 = (idx & 15) * 4;
            cp_async16(&Ks[(buf * 64 + hd) * 72 + c4], kb + hd * KTW + kt_ * 64 + c4, 16);
        }
    };
    auto issueV = [&](int kt_, int buf) {
#pragma unroll
        for (int i = 0; i < 4; i++) {
            int idx = t + i * 256;
            int row = idx >> 4, c4 = (idx & 15) * 4;
            int gk = kt_ * 64 + row;
            cp_async16(&Vs[(buf * 64 + row) * 72 + c4],
                       qb + (long long)gk * 2304 + 128 + c4, gk < Sc ? 16 : 0);
        }
    };
    issueK(0, 0);
    issueV(0, 0);
    asm volatile("cp.async.commit_group;\n");

    float accO[8][4] = {};
    float mr0 = -1e30f, mr1 = -1e30f, lr0 = 0.f, lr1 = 0.f;
    float* Pw = Ps + w * 16 * 68;
    const int nt = (Sc + 63) / 64;

    for (int kt_ = 0; kt_ < nt; kt_++) {
        int buf = kt_ & 1;
        __syncthreads();
        if (kt_ + 1 < nt) { issueK(kt_ + 1, buf ^ 1); issueV(kt_ + 1, buf ^ 1); }
        asm volatile("cp.async.commit_group;\n");
        asm volatile("cp.async.wait_group 1;\n");
        __syncthreads();

        float s[8][4] = {};
        const float* Kb = Ks + buf * 64 * 72;
#pragma unroll
        for (int ks = 0; ks < 8; ks++) {
            int kk = ks * 8;
            uint32_t af[4];
            af[0] = __float_as_uint(Qs[(w * 16 + g) * 68 + kk + tig]);
            af[1] = __float_as_uint(Qs[(w * 16 + g + 8) * 68 + kk + tig]);
            af[2] = __float_as_uint(Qs[(w * 16 + g) * 68 + kk + tig + 4]);
            af[3] = __float_as_uint(Qs[(w * 16 + g + 8) * 68 + kk + tig + 4]);
#pragma unroll
            for (int nf = 0; nf < 8; nf++) {
                uint32_t bf[2];
                bf[0] = __float_as_uint(Kb[(kk + tig) * 72 + nf * 8 + g]);
                bf[1] = __float_as_uint(Kb[(kk + tig + 4) * 72 + nf * 8 + g]);
                mma_tf32(s[nf], af, bf);
            }
        }
        float rm0 = -1e30f, rm1 = -1e30f;
#pragma unroll
        for (int nf = 0; nf < 8; nf++) {
#pragma unroll
            for (int cc = 0; cc < 4; cc++) {
                int col = kt_ * 64 + nf * 8 + tig * 2 + (cc & 1);
                float v = s[nf][cc] * 0.125f;
                v = (col < Sc) ? v : -1e30f;
                s[nf][cc] = v;
                if (cc < 2) rm0 = fmaxf(rm0, v); else rm1 = fmaxf(rm1, v);
            }
        }
        rm0 = fmaxf(rm0, __shfl_xor_sync(0xffffffffu, rm0, 1));
        rm0 = fmaxf(rm0, __shfl_xor_sync(0xffffffffu, rm0, 2));
        rm1 = fmaxf(rm1, __shfl_xor_sync(0xffffffffu, rm1, 1));
        rm1 = fmaxf(rm1, __shfl_xor_sync(0xffffffffu, rm1, 2));
        float nm0 = fmaxf(mr0, rm0), nm1 = fmaxf(mr1, rm1);
        float cor0 = __expf(mr0 - nm0), cor1 = __expf(mr1 - nm1);
        float rs0 = 0.f, rs1 = 0.f;
#pragma unroll
        for (int nf = 0; nf < 8; nf++) {
            int colb = nf * 8 + tig * 2;
            float p0 = __expf(s[nf][0] - nm0);
            float p1 = __expf(s[nf][1] - nm0);
            float p2 = __expf(s[nf][2] - nm1);
            float p3 = __expf(s[nf][3] - nm1);
            rs0 += p0 + p1; rs1 += p2 + p3;
            Pw[g * 68 + colb]       = f2tf_f(p0);
            Pw[g * 68 + colb + 1]   = f2tf_f(p1);
            Pw[(g + 8) * 68 + colb]     = f2tf_f(p2);
            Pw[(g + 8) * 68 + colb + 1] = f2tf_f(p3);
        }
        rs0 += __shfl_xor_sync(0xffffffffu, rs0, 1);
        rs0 += __shfl_xor_sync(0xffffffffu, rs0, 2);
        rs1 += __shfl_xor_sync(0xffffffffu, rs1, 1);
        rs1 += __shfl_xor_sync(0xffffffffu, rs1, 2);
        lr0 = lr0 * cor0 + rs0;
        lr1 = lr1 * cor1 + rs1;
        mr0 = nm0; mr1 = nm1;
#pragma unroll
        for (int nf = 0; nf < 8; nf++) {
            accO[nf][0] *= cor0; accO[nf][1] *= cor0;
            accO[nf][2] *= cor1; accO[nf][3] *= cor1;
        }
        __syncwarp();
        const float* Vb = Vs + buf * 64 * 72;
#pragma unroll
        for (int ks = 0; ks < 8; ks++) {
            int kk = ks * 8;
            uint32_t af[4];
            af[0] = __float_as_uint(Pw[g * 68 + kk + tig]);
            af[1] = __float_as_uint(Pw[(g + 8) * 68 + kk + tig]);
            af[2] = __float_as_uint(Pw[g * 68 + kk + tig + 4]);
            af[3] = __float_as_uint(Pw[(g + 8) * 68 + kk + tig + 4]);
#pragma unroll
            for (int nf = 0; nf < 8; nf++) {
                uint32_t bf[2];
                bf[0] = __float_as_uint(Vb[(kk + tig) * 72 + nf * 8 + g]);
                bf[1] = __float_as_uint(Vb[(kk + tig + 4) * 72 + nf * 8 + g]);
                mma_tf32(accO[nf], af, bf);
            }
        }
    }

    float inv0 = 1.0f / lr0, inv1 = 1.0f / lr1;
    int r0 = qt * 128 + w * 16 + g;
    int r1 = r0 + 8;
#pragma unroll
    for (int nf = 0; nf < 8; nf++) {
        int colb = nf * 8 + tig * 2;
        if (r0 < Sc) {
            om[((long long)b * Sc + r0) * Dc + h * 64 + colb]     = f2tf_f(accO[nf][0] * inv0);
            om[((long long)b * Sc + r0) * Dc + h * 64 + colb + 1] = f2tf_f(accO[nf][1] * inv0);
        }
        if (r1 < Sc) {
            om[((long long)b * Sc + r1) * Dc + h * 64 + colb]     = f2tf_f(accO[nf][2] * inv1);
            om[((long long)b * Sc + r1) * Dc + h * 64 + colb + 1] = f2tf_f(accO[nf][3] * inv1);
        }
    }
}

// ---------------- K transpose ----------------
__global__ void ktrans_kernel(const float* __restrict__ qkv, float* __restrict__ kT) {
    __shared__ float tile[32][33];
    int ktile = blockIdx.x;
    int hdt = blockIdx.y;
    int bh = blockIdx.z;
    int b = bh / Hc, h = bh % Hc;
    int tx = threadIdx.x, ty = threadIdx.y;
#pragma unroll
    for (int j = 0; j < 4; j++) {
        int key = ktile * 32 + ty + j * 8;
        int hd = hdt * 32 + tx;
        float v = 0.f;
        if (key < Sc) v = qkv[((long long)b * Sc + key) * 2304 + h * 192 + 64 + hd];
        tile[ty + j * 8][tx] = v;
    }
    __syncthreads();
#pragma unroll
    for (int j = 0; j < 4; j++) {
        int hd = hdt * 32 + ty + j * 8;
        int key = ktile * 32 + tx;
        kT[((long long)bh * HDc + hd) * KTW + key] = tile[tx][ty + j * 8];
    }
}

// ---------------- aux kernels ----------------
__global__ void im2col_kernel(const float* __restrict__ x, float* __restrict__ col) {
    long long idx = (long long)blockIdx.x * blockDim.x + threadIdx.x;
    long long total = (long long)Bc * NP * Dc;
    if (idx >= total) return;
    int k = (int)(idx % Dc);
    int rem = (int)(idx / Dc);
    int p = rem % NP;
    int b = rem / NP;
    int ph = p / GRID24, pw = p % GRID24;
    int ci = k / 256, k2 = k % 256;
    int kh = k2 / 16, kw = k2 % 16;
    col[idx] = f2tf_f(x[(((long long)b * 3 + ci) * IMGc + ph * 16 + kh) * IMGc + pw * 16 + kw]);
}

__global__ void transpose_convw_kernel(const float* __restrict__ w, float* __restrict__ wt) {
    int idx = blockIdx.x * blockDim.x + threadIdx.x;
    if (idx >= Dc * Dc) return;
    int k = idx / Dc, c = idx % Dc;
    wt[idx] = f2tf_f(w[c * Dc + k]);
}

__global__ void transpose_wqkv_kernel(const float* __restrict__ w, float* __restrict__ wt) {
    long long idx = (long long)blockIdx.x * blockDim.x + threadIdx.x;
    long long total = (long long)Lc * Dc * 3 * Dc;
    if (idx >= total) return;
    int n = (int)(idx % (3 * Dc));
    int rem = (int)(idx / (3 * Dc));
    int d = rem % Dc;
    int l = rem / Dc;
    int h = n / 192, e = n % 192;
    wt[idx] = f2tf_f(w[(((long long)l * Hc + h) * Dc + d) * 192 + e]);
}

__global__ void round_copy_kernel(const float* __restrict__ w, float* __restrict__ o, long long n) {
    long long i = (long long)blockIdx.x * blockDim.x + threadIdx.x;
    if (i < n) o[i] = f2tf_f(w[i]);
}

__global__ void embed_kernel(const float* __restrict__ pout, const float* __restrict__ cls,
                             const float* __restrict__ pos, float* __restrict__ t) {
    long long idx = (long long)blockIdx.x * blockDim.x + threadIdx.x;
    long long total = (long long)Bc * Sc * Dc;
    if (idx >= total) return;
    int j = (int)(idx % Dc);
    int rem = (int)(idx / Dc);
    int r = rem % Sc;
    int b = rem / Sc;
    float v;
    if (r == 0) {
        v = cls[j];
    } else {
        int i = (r - 1) * Dc + j;
        int c = i / NP, p = i % NP;
        v = pout[((long long)b * NP + p) * Dc + c];
    }
    t[idx] = v + pos[r * Dc + j];
}

__global__ void layernorm_kernel(const float* __restrict__ x, const float* __restrict__ g,
                                 const float* __restrict__ b, float* __restrict__ y, int rows) {
    __shared__ float red[256];
    int row = blockIdx.x;
    if (row >= rows) return;
    int t = threadIdx.x;
    const float* xr = x + (long long)row * Dc;
    float v[3];
    float s = 0.f;
#pragma unroll
    for (int i = 0; i < 3; i++) { v[i] = xr[t + i * 256]; s += v[i]; }
    red[t] = s; __syncthreads();
    for (int o = 128; o > 0; o >>= 1) { if (t < o) red[t] += red[t + o]; __syncthreads(); }
    float mu = red[0] / Dc;
    __syncthreads();
    float s2 = 0.f;
#pragma unroll
    for (int i = 0; i < 3; i++) { float d = v[i] - mu; s2 += d * d; }
    red[t] = s2; __syncthreads();
    for (int o = 128; o > 0; o >>= 1) { if (t < o) red[t] += red[t + o]; __syncthreads(); }
    float rstd = rsqrtf(red[0] / Dc + 1e-5f);
    float* yr = y + (long long)row * Dc;
#pragma unroll
    for (int i = 0; i < 3; i++) {
        int j = t + i * 256;
        yr[j] = f2tf_f((v[i] - mu) * rstd * g[j] + b[j]);
    }
}

// fused double layernorm: y = tf32( LN(LN(x, g1,b1), g2,b2) )
__global__ void layernorm2_kernel(const float* __restrict__ x,
                                  const float* __restrict__ g1, const float* __restrict__ b1,
                                  const float* __restrict__ g2, const float* __restrict__ b2,
                                  float* __restrict__ y, int rows) {
    __shared__ float red[256];
    int row = blockIdx.x;
    if (row >= rows) return;
    int t = threadIdx.x;
    const float* xr = x + (long long)row * Dc;
    float v[3];
    float s = 0.f;
#pragma unroll
    for (int i = 0; i < 3; i++) { v[i] = xr[t + i * 256]; s += v[i]; }
    red[t] = s; __syncthreads();
    for (int o = 128; o > 0; o >>= 1) { if (t < o) red[t] += red[t + o]; __syncthreads(); }
    float mu = red[0] / Dc;
    __syncthreads();
    float s2 = 0.f;
#pragma unroll
    for (int i = 0; i < 3; i++) { float d = v[i] - mu; s2 += d * d; }
    red[t] = s2; __syncthreads();
    for (int o = 128; o > 0; o >>= 1) { if (t < o) red[t] += red[t + o]; __syncthreads(); }
    float rstd = rsqrtf(red[0] / Dc + 1e-5f);
    __syncthreads();
    // first LN -> v
    s = 0.f;
#pragma unroll
    for (int i = 0; i < 3; i++) {
        int j = t + i * 256;
        v[i] = (v[i] - mu) * rstd * g1[j] + b1[j];
        s += v[i];
    }
    red[t] = s; __syncthreads();
    for (int o = 128; o > 0; o >>= 1) { if (t < o) red[t] += red[t + o]; __syncthreads(); }
    mu = red[0] / Dc;
    __syncthreads();
    s2 = 0.f;
#pragma unroll
    for (int i = 0; i < 3; i++) { float d = v[i] - mu; s2 += d * d; }
    red[t] = s2; __syncthreads();
    for (int o = 128; o > 0; o >>= 1) { if (t < o) red[t] += red[t + o]; __syncthreads(); }
    rstd = rsqrtf(red[0] / Dc + 1e-5f);
    float* yr = y + (long long)row * Dc;
#pragma unroll
    for (int i = 0; i < 3; i++) {
        int j = t + i * 256;
        yr[j] = f2tf_f((v[i] - mu) * rstd * g2[j] + b2[j]);
    }
}

__global__ void softmax_kernel(float* __restrict__ x, long long rows, int n) {
    __shared__ float red[256];
    long long row = blockIdx.x;
    if (row >= rows) return;
    int t = threadIdx.x;
    float* xr = x + row * n;
    float lmax = -1e30f;
    for (int j = t; j < n; j += 256) lmax = fmaxf(lmax, xr[j]);
    red[t] = lmax; __syncthreads();
    for (int o = 128; o > 0; o >>= 1) { if (t < o) red[t] = fmaxf(red[t], red[t + o]); __syncthreads(); }
    float mx = red[0];
    __syncthreads();
    float ls = 0.f;
    for (int j = t; j < n; j += 256) { float e = expf(xr[j] - mx); xr[j] = e; ls += e; }
    red[t] = ls; __syncthreads();
    for (int o = 128; o > 0; o >>= 1) { if (t < o) red[t] += red[t + o]; __syncthreads(); }
    float inv = 1.0f / red[0];
    for (int j = t; j < n; j += 256) xr[j] *= inv;
}

__global__ void extract_cls_kernel(const float* __restrict__ t, float* __restrict__ cls) {
    int idx = blockIdx.x * blockDim.x + threadIdx.x;
    if (idx >= Bc * Dc) return;
    int b = idx / Dc, j = idx % Dc;
    cls[idx] = t[((long long)b * Sc) * Dc + j];
}

// ---------------- host helpers ----------------
static const int GEMM_SMEM = GS * (2560 + 2176) * 4;  // 75776 bytes

static void run_gemm(const float* A, const float* Bm, const float* bias,
                     const float* res, float* C, int M, int N, int K,
                     int lda, int ldb, int ldc, int act, int rnd) {
    dim3 grid((N + 127) / 128, (M + 127) / 128, 1);
    mma_gemm_kernel<<<grid, 128, GEMM_SMEM>>>(A, Bm, bias, res, C, M, N, K, lda, ldb, ldc, act, rnd);
}

extern "C" void kernel_launch(void* const* d_in, const int* in_sizes, int n_in,
                              void* d_out, int out_size) {
    const float* x       = (const float*)d_in[0];
    const float* conv_w  = (const float*)d_in[1];
    const float* conv_b  = (const float*)d_in[2];
    const float* cls_tok = (const float*)d_in[3];
    const float* pos_emb = (const float*)d_in[4];
    const float* ln1_g   = (const float*)d_in[5];
    const float* ln1_b   = (const float*)d_in[6];
    const float* wqkv    = (const float*)d_in[7];
    const float* bqkv    = (const float*)d_in[8];
    const float* wmsa    = (const float*)d_in[9];
    const float* bmsa    = (const float*)d_in[10];
    const float* ln2_g   = (const float*)d_in[11];
    const float* ln2_b   = (const float*)d_in[12];
    const float* lnm_g   = (const float*)d_in[13];
    const float* lnm_b   = (const float*)d_in[14];
    const float* w1      = (const float*)d_in[15];
    const float* b1      = (const float*)d_in[16];
    const float* w2      = (const float*)d_in[17];
    const float* b2      = (const float*)d_in[18];
    const float* lnf_g   = (const float*)d_in[19];
    const float* lnf_b   = (const float*)d_in[20];
    const float* whead   = (const float*)d_in[21];
    const float* bhead   = (const float*)d_in[22];
    float* out = (float*)d_out;

    float *t_, *h_, *om_, *qkv_, *mb_, *col_, *wtq_, *cwt_, *cls_, *kT_;
    float *wmsar_, *w1r_, *w2r_, *whr_;
    cudaGetSymbolAddress((void**)&t_,  g_t);
    cudaGetSymbolAddress((void**)&h_,  g_h);
    cudaGetSymbolAddress((void**)&om_, g_om);
    cudaGetSymbolAddress((void**)&qkv_, g_qkv);
    cudaGetSymbolAddress((void**)&mb_, g_mbuf);
    cudaGetSymbolAddress((void**)&col_, g_col);
    cudaGetSymbolAddress((void**)&wtq_, g_wtqkv);
    cudaGetSymbolAddress((void**)&cwt_, g_cwt);
    cudaGetSymbolAddress((void**)&cls_, g_cls);
    cudaGetSymbolAddress((void**)&kT_, g_kT);
    cudaGetSymbolAddress((void**)&wmsar_, g_wmsar);
    cudaGetSymbolAddress((void**)&w1r_, g_w1r);
    cudaGetSymbolAddress((void**)&w2r_, g_w2r);
    cudaGetSymbolAddress((void**)&whr_, g_whr);

    cudaFuncSetAttribute(flash_kernel, cudaFuncAttributeMaxDynamicSharedMemorySize, 143360);
    cudaFuncSetAttribute(mma_gemm_kernel, cudaFuncAttributeMaxDynamicSharedMemorySize, GEMM_SMEM);

    // --- weight re-layouts / tf32 pre-rounding ---
    transpose_convw_kernel<<<(Dc * Dc + 255) / 256, 256>>>(conv_w, cwt_);
    {
        long long tot = (long long)Lc * Dc * 3 * Dc;
        transpose_wqkv_kernel<<<(int)((tot + 255) / 256), 256>>>(wqkv, wtq_);
    }
    {
        long long n1 = (long long)Lc * Dc * Dc;
        round_copy_kernel<<<(int)((n1 + 255) / 256), 256>>>(wmsa, wmsar_, n1);
        long long n2 = (long long)Lc * Dc * Mc;
        round_copy_kernel<<<(int)((n2 + 255) / 256), 256>>>(w1, w1r_, n2);
        round_copy_kernel<<<(int)((n2 + 255) / 256), 256>>>(w2, w2r_, n2);
        long long n3 = (long long)Dc * NCc;
        round_copy_kernel<<<(int)((n3 + 255) / 256), 256>>>(whead, whr_, n3);
    }

    // --- patchify ---
    {
        long long tot = (long long)Bc * NP * Dc;
        im2col_kernel<<<(int)((tot + 255) / 256), 256>>>(x, col_);
    }
    run_gemm(col_, cwt_, conv_b, nullptr, h_, Bc * NP, Dc, Dc, Dc, Dc, Dc, 0, 0);
    {
        long long tot = (long long)Bc * Sc * Dc;
        embed_kernel<<<(int)((tot + 255) / 256), 256>>>(h_, cls_tok, pos_emb, t_);
    }

    // --- encoder layers ---
    for (int l = 0; l < Lc; l++) {
        layernorm_kernel<<<BS, 256>>>(t_, ln1_g + l * Dc, ln1_b + l * Dc, h_, BS);
        run_gemm(h_, wtq_ + (long long)l * Dc * 3 * Dc, bqkv + l * 3 * Dc, nullptr,
                 qkv_, BS, 3 * Dc, Dc, Dc, 3 * Dc, 3 * Dc, 0, 1);
        ktrans_kernel<<<dim3(KTW / 32, 2, Bc * Hc), dim3(32, 8)>>>(qkv_, kT_);
        flash_kernel<<<dim3((Sc + 127) / 128, Hc, Bc), 256, 143360>>>(qkv_, kT_, om_);
        run_gemm(om_, wmsar_ + (long long)l * Dc * Dc, bmsa + l * Dc, h_, t_,
                 BS, Dc, Dc, Dc, Dc, Dc, 0, 0);
        layernorm2_kernel<<<BS, 256>>>(t_, ln2_g + l * Dc, ln2_b + l * Dc,
                                       lnm_g + l * Dc, lnm_b + l * Dc, h_, BS);
        run_gemm(h_, w1r_ + (long long)l * Dc * Mc, b1 + l * Mc, nullptr, mb_,
                 BS, Mc, Dc, Dc, Mc, Mc, 1, 1);
        run_gemm(mb_, w2r_ + (long long)l * Mc * Dc, b2 + l * Dc, t_, t_,
                 BS, Dc, Mc, Mc, Dc, Dc, 0, 0);
    }

    // --- head ---
    extract_cls_kernel<<<(Bc * Dc + 255) / 256, 256>>>(t_, cls_);
    layernorm_kernel<<<Bc, 256>>>(cls_, lnf_g, lnf_b, cls_, Bc);
    run_gemm(cls_, whr_, bhead, nullptr, out, Bc, NCc, Dc, Dc, NCc, NCc, 0, 0);
    softmax_kernel<<<Bc, 256>>>(out, Bc, NCc);
}

// round 6
// speedup vs baseline: 1.1043x; 1.1043x over previous
#include <cuda_runtime.h>
#include <math.h>
#include <stdint.h>

// ---------------- dims ----------------
static const int Lc = 12, Hc = 12, Dc = 768, HDc = 64, Mc = 3072;
static const int IMGc = 384, Bc = 32, NCc = 1000;
static const int NP = 576;
static const int Sc = 577;
static const int BS = Bc * Sc;        // 18464
static const int GRID24 = 24;
static const int KTW = 640;
static const int GS = 4;              // gemm pipeline stages

// ---------------- scratch ----------------
__device__ float g_t[BS * Dc];
__device__ float g_h[BS * Dc];
__device__ float g_om[BS * Dc];
__device__ float g_qkv[BS * 3 * Dc];
__device__ float g_mbuf[BS * Mc];
__device__ float g_col[Bc * NP * Dc];
__device__ float g_wtqkv[Lc * 3 * Dc * Dc];   // [l][n=2304][k=768]
__device__ float g_cwt[Dc * Dc];              // conv_w rounded, already [n][k]
__device__ float g_cls[Bc * Dc];
__device__ float g_kT[(long long)Bc * Hc * HDc * KTW];
__device__ float g_wmsar[Lc * Dc * Dc];       // [l][d_out][d_in]
__device__ float g_w1r[Lc * Mc * Dc];         // [l][m][d]
__device__ float g_w2r[Lc * Dc * Mc];         // [l][d][m]
__device__ float g_whr[NCc * Dc];             // [nc][d]

// ---------------- tf32 helpers ----------------
__device__ __forceinline__ uint32_t f2tf(float f) {
    uint32_t u;
    asm("cvt.rna.tf32.f32 %0, %1;" : "=r"(u) : "f"(f));
    return u;
}
__device__ __forceinline__ float f2tf_f(float f) { return __uint_as_float(f2tf(f)); }

__device__ __forceinline__ void mma_tf32(float c[4], const uint32_t a[4], const uint32_t b[2]) {
    asm volatile(
        "mma.sync.aligned.m16n8k8.row.col.f32.tf32.tf32.f32 "
        "{%0,%1,%2,%3}, {%4,%5,%6,%7}, {%8,%9}, {%0,%1,%2,%3};\n"
        : "+f"(c[0]), "+f"(c[1]), "+f"(c[2]), "+f"(c[3])
        : "r"(a[0]), "r"(a[1]), "r"(a[2]), "r"(a[3]), "r"(b[0]), "r"(b[1]));
}

__device__ __forceinline__ void cp_async16(void* smem_dst, const void* gsrc, int sz) {
    unsigned sm = (unsigned)__cvta_generic_to_shared(smem_dst);
    asm volatile("cp.async.ca.shared.global [%0], [%1], 16, %2;\n" :: "r"(sm), "l"(gsrc), "r"(sz));
}

__device__ __forceinline__ void ldsm4(uint32_t r[4], const float* p) {
    unsigned a = (unsigned)__cvta_generic_to_shared(p);
    asm volatile("ldmatrix.sync.aligned.m8n8.x4.shared.b16 {%0,%1,%2,%3}, [%4];\n"
                 : "=r"(r[0]), "=r"(r[1]), "=r"(r[2]), "=r"(r[3]) : "r"(a));
}

// ---------------- dense tf32 GEMM: both operands K-major, ldmatrix frags ----------------
// C[M,N] = act( A[m][k] @ B[n][k]^T + bias + res ). B is pre-transposed weights.
// CTA 128x128, 8 warps (2x4) of 64x32, BK=16, GS-stage cp.async pipeline.
// dynamic smem: per stage: A[128][20] then B[128][20]  (5120 floats)
__global__ void __launch_bounds__(256, 2)
mma_gemm_kernel(const float* __restrict__ A, const float* __restrict__ Bm,
                const float* __restrict__ bias, const float* __restrict__ res,
                float* __restrict__ C,
                int M, int N, int K, int lda, int ldb, int ldc,
                int act, int rnd) {
    extern __shared__ float sm[];

    int t = threadIdx.x;
    int lane = t & 31, wid = t >> 5;
    int wm = wid >> 2, wn = wid & 3;          // 2 x 4 warps
    int g = lane >> 2, tig = lane & 3;
    int m0 = blockIdx.y * 128, n0 = blockIdx.x * 128;

    float acc[4][4][4] = {};
    int nk = K / 16;

    auto loadTile = [&](int k0, int s) {
        float* dstA = sm + s * 5120;
        float* dstB = dstA + 2560;
#pragma unroll
        for (int i = 0; i < 2; i++) {
            int c = t + i * 256;
            int m = c >> 2, kq = (c & 3) * 4;
            cp_async16(dstA + m * 20 + kq, A + (long long)(m0 + m) * lda + k0 + kq,
                       (m0 + m < M) ? 16 : 0);
        }
#pragma unroll
        for (int i = 0; i < 2; i++) {
            int c = t + i * 256;
            int n = c >> 2, kq = (c & 3) * 4;
            cp_async16(dstB + n * 20 + kq, Bm + (long long)(n0 + n) * ldb + k0 + kq,
                       (n0 + n < N) ? 16 : 0);
        }
    };

#pragma unroll
    for (int s = 0; s < GS - 1; s++) {
        loadTile(s * 16, s);
        asm volatile("cp.async.commit_group;\n");
    }

    int arow = wm * 64 + (lane & 15);
    int brow = wn * 32 + (lane & 15);
    int colb = 4 * (lane >> 4);               // 0 or 4

    for (int it = 0; it < nk; it++) {
        asm volatile("cp.async.wait_group %0;\n" :: "n"(GS - 2));
        __syncthreads();
        if (it + GS - 1 < nk) loadTile((it + GS - 1) * 16, (it + GS - 1) % GS);
        asm volatile("cp.async.commit_group;\n");

        int s = it % GS;
        const float* Ab = sm + s * 5120;
        const float* Bb = Ab + 2560;
#pragma unroll
        for (int ks = 0; ks < 2; ks++) {
            int kc = ks * 8 + colb;
            uint32_t af[4][4], bq[2][4];
#pragma unroll
            for (int mt = 0; mt < 4; mt++)
                ldsm4(af[mt], Ab + (arow + mt * 16) * 20 + kc);
#pragma unroll
            for (int nh = 0; nh < 2; nh++)
                ldsm4(bq[nh], Bb + (brow + nh * 16) * 20 + kc);
#pragma unroll
            for (int mt = 0; mt < 4; mt++)
#pragma unroll
                for (int nt = 0; nt < 4; nt++) {
                    uint32_t b2[2] = { bq[nt >> 1][nt & 1], bq[nt >> 1][2 + (nt & 1)] };
                    mma_tf32(acc[mt][nt], af[mt], b2);
                }
        }
    }

    // epilogue
#pragma unroll
    for (int mt = 0; mt < 4; mt++) {
#pragma unroll
        for (int nt = 0; nt < 4; nt++) {
            int row = m0 + wm * 64 + mt * 16 + g;
            int col = n0 + wn * 32 + nt * 8 + tig * 2;
#pragma unroll
            for (int cc = 0; cc < 4; cc++) {
                int m = row + (cc >> 1) * 8;
                int n = col + (cc & 1);
                if (m >= M || n >= N) continue;
                float v = acc[mt][nt][cc];
                if (bias) v += bias[n];
                if (res) v += res[(long long)m * ldc + n];
                if (act == 1) v = 0.5f * v * (1.0f + erff(v * 0.7071067811865476f));
                if (rnd) v = f2tf_f(v);
                C[(long long)m * ldc + n] = v;
            }
        }
    }
}

// ---------------- fused flash attention (unchanged) ----------------
__global__ void __launch_bounds__(256)
flash_kernel(const float* __restrict__ qkv, const float* __restrict__ kT,
             float* __restrict__ om) {
    extern __shared__ float smf[];
    float* Qs = smf;               // [128][68]
    float* Ps = smf + 8704;        // [8][16][68]
    float* Ks = smf + 17408;       // [2][64][72]
    float* Vs = smf + 26624;       // [2][64][72]

    int qt = blockIdx.x, h = blockIdx.y, b = blockIdx.z;
    int t = threadIdx.x, lane = t & 31, w = t >> 5, g = lane >> 2, tig = lane & 3;
    const float* qb = qkv + (long long)b * Sc * 2304 + h * 192;
    const float* kb = kT + ((long long)(b * Hc + h)) * HDc * KTW;

#pragma unroll
    for (int i = 0; i < 8; i++) {
        int idx = t + i * 256;
        int row = idx >> 4, c4 = (idx & 15) * 4;
        int gr = qt * 128 + row;
        cp_async16(&Qs[row * 68 + c4], qb + (long long)gr * 2304 + c4, gr < Sc ? 16 : 0);
    }
    auto issueK = [&](int kt_, int buf) {
#pragma unroll
        for (int i = 0; i < 4; i++) {
            int idx = t + i * 256;
            int hd = idx >> 4, c4 = (idx & 15) * 4;
            cp_async16(&Ks[(buf * 64 + hd) * 72 + c4], kb + hd * KTW + kt_ * 64 + c4, 16);
        }
    };
    auto issueV = [&](int kt_, int buf) {
#pragma unroll
        for (int i = 0; i < 4; i++) {
            int idx = t + i * 256;
            int row = idx >> 4, c4 = (idx & 15) * 4;
            int gk = kt_ * 64 + row;
            cp_async16(&Vs[(buf * 64 + row) * 72 + c4],
                       qb + (long long)gk * 2304 + 128 + c4, gk < Sc ? 16 : 0);
        }
    };
    issueK(0, 0);
    issueV(0, 0);
    asm volatile("cp.async.commit_group;\n");

    float accO[8][4] = {};
    float mr0 = -1e30f, mr1 = -1e30f, lr0 = 0.f, lr1 = 0.f;
    float* Pw = Ps + w * 16 * 68;
    const int nt = (Sc + 63) / 64;

    for (int kt_ = 0; kt_ < nt; kt_++) {
        int buf = kt_ & 1;
        __syncthreads();
        if (kt_ + 1 < nt) { issueK(kt_ + 1, buf ^ 1); issueV(kt_ + 1, buf ^ 1); }
        asm volatile("cp.async.commit_group;\n");
        asm volatile("cp.async.wait_group 1;\n");
        __syncthreads();

        float s[8][4] = {};
        const float* Kb = Ks + buf * 64 * 72;
#pragma unroll
        for (int ks = 0; ks < 8; ks++) {
            int kk = ks * 8;
            uint32_t af[4];
            af[0] = __float_as_uint(Qs[(w * 16 + g) * 68 + kk + tig]);
            af[1] = __float_as_uint(Qs[(w * 16 + g + 8) * 68 + kk + tig]);
            af[2] = __float_as_uint(Qs[(w * 16 + g) * 68 + kk + tig + 4]);
            af[3] = __float_as_uint(Qs[(w * 16 + g + 8) * 68 + kk + tig + 4]);
#pragma unroll
            for (int nf = 0; nf < 8; nf++) {
                uint32_t bf[2];
                bf[0] = __float_as_uint(Kb[(kk + tig) * 72 + nf * 8 + g]);
                bf[1] = __float_as_uint(Kb[(kk + tig + 4) * 72 + nf * 8 + g]);
                mma_tf32(s[nf], af, bf);
            }
        }
        float rm0 = -1e30f, rm1 = -1e30f;
#pragma unroll
        for (int nf = 0; nf < 8; nf++) {
#pragma unroll
            for (int cc = 0; cc < 4; cc++) {
                int col = kt_ * 64 + nf * 8 + tig * 2 + (cc & 1);
                float v = s[nf][cc] * 0.125f;
                v = (col < Sc) ? v : -1e30f;
                s[nf][cc] = v;
                if (cc < 2) rm0 = fmaxf(rm0, v); else rm1 = fmaxf(rm1, v);
            }
        }
        rm0 = fmaxf(rm0, __shfl_xor_sync(0xffffffffu, rm0, 1));
        rm0 = fmaxf(rm0, __shfl_xor_sync(0xffffffffu, rm0, 2));
        rm1 = fmaxf(rm1, __shfl_xor_sync(0xffffffffu, rm1, 1));
        rm1 = fmaxf(rm1, __shfl_xor_sync(0xffffffffu, rm1, 2));
        float nm0 = fmaxf(mr0, rm0), nm1 = fmaxf(mr1, rm1);
        float cor0 = __expf(mr0 - nm0), cor1 = __expf(mr1 - nm1);
        float rs0 = 0.f, rs1 = 0.f;
#pragma unroll
        for (int nf = 0; nf < 8; nf++) {
            int colb = nf * 8 + tig * 2;
            float p0 = __expf(s[nf][0] - nm0);
            float p1 = __expf(s[nf][1] - nm0);
            float p2 = __expf(s[nf][2] - nm1);
            float p3 = __expf(s[nf][3] - nm1);
            rs0 += p0 + p1; rs1 += p2 + p3;
            Pw[g * 68 + colb]       = f2tf_f(p0);
            Pw[g * 68 + colb + 1]   = f2tf_f(p1);
            Pw[(g + 8) * 68 + colb]     = f2tf_f(p2);
            Pw[(g + 8) * 68 + colb + 1] = f2tf_f(p3);
        }
        rs0 += __shfl_xor_sync(0xffffffffu, rs0, 1);
        rs0 += __shfl_xor_sync(0xffffffffu, rs0, 2);
        rs1 += __shfl_xor_sync(0xffffffffu, rs1, 1);
        rs1 += __shfl_xor_sync(0xffffffffu, rs1, 2);
        lr0 = lr0 * cor0 + rs0;
        lr1 = lr1 * cor1 + rs1;
        mr0 = nm0; mr1 = nm1;
#pragma unroll
        for (int nf = 0; nf < 8; nf++) {
            accO[nf][0] *= cor0; accO[nf][1] *= cor0;
            accO[nf][2] *= cor1; accO[nf][3] *= cor1;
        }
        __syncwarp();
        const float* Vb = Vs + buf * 64 * 72;
#pragma unroll
        for (int ks = 0; ks < 8; ks++) {
            int kk = ks * 8;
            uint32_t af[4];
            af[0] = __float_as_uint(Pw[g * 68 + kk + tig]);
            af[1] = __float_as_uint(Pw[(g + 8) * 68 + kk + tig]);
            af[2] = __float_as_uint(Pw[g * 68 + kk + tig + 4]);
            af[3] = __float_as_uint(Pw[(g + 8) * 68 + kk + tig + 4]);
#pragma unroll
            for (int nf = 0; nf < 8; nf++) {
                uint32_t bf[2];
                bf[0] = __float_as_uint(Vb[(kk + tig) * 72 + nf * 8 + g]);
                bf[1] = __float_as_uint(Vb[(kk + tig + 4) * 72 + nf * 8 + g]);
                mma_tf32(accO[nf], af, bf);
            }
        }
    }

    float inv0 = 1.0f / lr0, inv1 = 1.0f / lr1;
    int r0 = qt * 128 + w * 16 + g;
    int r1 = r0 + 8;
#pragma unroll
    for (int nf = 0; nf < 8; nf++) {
        int colb = nf * 8 + tig * 2;
        if (r0 < Sc) {
            om[((long long)b * Sc + r0) * Dc + h * 64 + colb]     = f2tf_f(accO[nf][0] * inv0);
            om[((long long)b * Sc + r0) * Dc + h * 64 + colb + 1] = f2tf_f(accO[nf][1] * inv0);
        }
        if (r1 < Sc) {
            om[((long long)b * Sc + r1) * Dc + h * 64 + colb]     = f2tf_f(accO[nf][2] * inv1);
            om[((long long)b * Sc + r1) * Dc + h * 64 + colb + 1] = f2tf_f(accO[nf][3] * inv1);
        }
    }
}

// ---------------- K transpose ----------------
__global__ void ktrans_kernel(const float* __restrict__ qkv, float* __restrict__ kT) {
    __shared__ float tile[32][33];
    int ktile = blockIdx.x;
    int hdt = blockIdx.y;
    int bh = blockIdx.z;
    int b = bh / Hc, h = bh % Hc;
    int tx = threadIdx.x, ty = threadIdx.y;
#pragma unroll
    for (int j = 0; j < 4; j++) {
        int key = ktile * 32 + ty + j * 8;
        int hd = hdt * 32 + tx;
        float v = 0.f;
        if (key < Sc) v = qkv[((long long)b * Sc + key) * 2304 + h * 192 + 64 + hd];
        tile[ty + j * 8][tx] = v;
    }
    __syncthreads();
#pragma unroll
    for (int j = 0; j < 4; j++) {
        int hd = hdt * 32 + ty + j * 8;
        int key = ktile * 32 + tx;
        kT[((long long)bh * HDc + hd) * KTW + key] = tile[tx][ty + j * 8];
    }
}

// ---------------- aux kernels ----------------
__global__ void im2col_kernel(const float* __restrict__ x, float* __restrict__ col) {
    long long idx = (long long)blockIdx.x * blockDim.x + threadIdx.x;
    long long total = (long long)Bc * NP * Dc;
    if (idx >= total) return;
    int k = (int)(idx % Dc);
    int rem = (int)(idx / Dc);
    int p = rem % NP;
    int b = rem / NP;
    int ph = p / GRID24, pw = p % GRID24;
    int ci = k / 256, k2 = k % 256;
    int kh = k2 / 16, kw = k2 % 16;
    col[idx] = f2tf_f(x[(((long long)b * 3 + ci) * IMGc + ph * 16 + kh) * IMGc + pw * 16 + kw]);
}

// transpose wqkv to [l][n=2304][k=768], rounded
__global__ void transpose_wqkv_kernel(const float* __restrict__ w, float* __restrict__ wt) {
    long long idx = (long long)blockIdx.x * blockDim.x + threadIdx.x;
    long long total = (long long)Lc * 3 * Dc * Dc;
    if (idx >= total) return;
    int d = (int)(idx % Dc);
    int rem = (int)(idx / Dc);
    int n = rem % (3 * Dc);
    int l = rem / (3 * Dc);
    int h = n / 192, e = n % 192;
    wt[idx] = f2tf_f(w[(((long long)l * Hc + h) * Dc + d) * 192 + e]);
}

// generic batched transpose with tf32 round: out[l][c][r] = round(in[l][r][c])
__global__ void btrans_kernel(const float* __restrict__ in, float* __restrict__ out,
                              int R, int Cn) {
    __shared__ float tile[32][33];
    int ct = blockIdx.x, rt = blockIdx.y, l = blockIdx.z;
    const float* inl = in + (long long)l * R * Cn;
    float* outl = out + (long long)l * R * Cn;
    int tx = threadIdx.x, ty = threadIdx.y;   // 32 x 8
#pragma unroll
    for (int j = 0; j < 4; j++) {
        int r = rt * 32 + ty + j * 8;
        int c = ct * 32 + tx;
        tile[ty + j * 8][tx] = (r < R && c < Cn) ? inl[(long long)r * Cn + c] : 0.f;
    }
    __syncthreads();
#pragma unroll
    for (int j = 0; j < 4; j++) {
        int c = ct * 32 + ty + j * 8;
        int r = rt * 32 + tx;
        if (c < Cn && r < R)
            outl[(long long)c * R + r] = f2tf_f(tile[tx][ty + j * 8]);
    }
}

__global__ void round_copy_kernel(const float* __restrict__ w, float* __restrict__ o, long long n) {
    long long i = (long long)blockIdx.x * blockDim.x + threadIdx.x;
    if (i < n) o[i] = f2tf_f(w[i]);
}

__global__ void embed_kernel(const float* __restrict__ pout, const float* __restrict__ cls,
                             const float* __restrict__ pos, float* __restrict__ t) {
    long long idx = (long long)blockIdx.x * blockDim.x + threadIdx.x;
    long long total = (long long)Bc * Sc * Dc;
    if (idx >= total) return;
    int j = (int)(idx % Dc);
    int rem = (int)(idx / Dc);
    int r = rem % Sc;
    int b = rem / Sc;
    float v;
    if (r == 0) {
        v = cls[j];
    } else {
        int i = (r - 1) * Dc + j;
        int c = i / NP, p = i % NP;
        v = pout[((long long)b * NP + p) * Dc + c];
    }
    t[idx] = v + pos[r * Dc + j];
}

__global__ void layernorm_kernel(const float* __restrict__ x, const float* __restrict__ g,
                                 const float* __restrict__ b, float* __restrict__ y, int rows) {
    __shared__ float red[256];
    int row = blockIdx.x;
    if (row >= rows) return;
    int t = threadIdx.x;
    const float* xr = x + (long long)row * Dc;
    float v[3];
    float s = 0.f;
#pragma unroll
    for (int i = 0; i < 3; i++) { v[i] = xr[t + i * 256]; s += v[i]; }
    red[t] = s; __syncthreads();
    for (int o = 128; o > 0; o >>= 1) { if (t < o) red[t] += red[t + o]; __syncthreads(); }
    float mu = red[0] / Dc;
    __syncthreads();
    float s2 = 0.f;
#pragma unroll
    for (int i = 0; i < 3; i++) { float d = v[i] - mu; s2 += d * d; }
    red[t] = s2; __syncthreads();
    for (int o = 128; o > 0; o >>= 1) { if (t < o) red[t] += red[t + o]; __syncthreads(); }
    float rstd = rsqrtf(red[0] / Dc + 1e-5f);
    float* yr = y + (long long)row * Dc;
#pragma unroll
    for (int i = 0; i < 3; i++) {
        int j = t + i * 256;
        yr[j] = f2tf_f((v[i] - mu) * rstd * g[j] + b[j]);
    }
}

// fused double layernorm
__global__ void layernorm2_kernel(const float* __restrict__ x,
                                  const float* __restrict__ g1, const float* __restrict__ b1,
                                  const float* __restrict__ g2, const float* __restrict__ b2,
                                  float* __restrict__ y, int rows) {
    __shared__ float red[256];
    int row = blockIdx.x;
    if (row >= rows) return;
    int t = threadIdx.x;
    const float* xr = x + (long long)row * Dc;
    float v[3];
    float s = 0.f;
#pragma unroll
    for (int i = 0; i < 3; i++) { v[i] = xr[t + i * 256]; s += v[i]; }
    red[t] = s; __syncthreads();
    for (int o = 128; o > 0; o >>= 1) { if (t < o) red[t] += red[t + o]; __syncthreads(); }
    float mu = red[0] / Dc;
    __syncthreads();
    float s2 = 0.f;
#pragma unroll
    for (int i = 0; i < 3; i++) { float d = v[i] - mu; s2 += d * d; }
    red[t] = s2; __syncthreads();
    for (int o = 128; o > 0; o >>= 1) { if (t < o) red[t] += red[t + o]; __syncthreads(); }
    float rstd = rsqrtf(red[0] / Dc + 1e-5f);
    __syncthreads();
    s = 0.f;
#pragma unroll
    for (int i = 0; i < 3; i++) {
        int j = t + i * 256;
        v[i] = (v[i] - mu) * rstd * g1[j] + b1[j];
        s += v[i];
    }
    red[t] = s; __syncthreads();
    for (int o = 128; o > 0; o >>= 1) { if (t < o) red[t] += red[t + o]; __syncthreads(); }
    mu = red[0] / Dc;
    __syncthreads();
    s2 = 0.f;
#pragma unroll
    for (int i = 0; i < 3; i++) { float d = v[i] - mu; s2 += d * d; }
    red[t] = s2; __syncthreads();
    for (int o = 128; o > 0; o >>= 1) { if (t < o) red[t] += red[t + o]; __syncthreads(); }
    rstd = rsqrtf(red[0] / Dc + 1e-5f);
    float* yr = y + (long long)row * Dc;
#pragma unroll
    for (int i = 0; i < 3; i++) {
        int j = t + i * 256;
        yr[j] = f2tf_f((v[i] - mu) * rstd * g2[j] + b2[j]);
    }
}

__global__ void softmax_kernel(float* __restrict__ x, long long rows, int n) {
    __shared__ float red[256];
    long long row = blockIdx.x;
    if (row >= rows) return;
    int t = threadIdx.x;
    float* xr = x + row * n;
    float lmax = -1e30f;
    for (int j = t; j < n; j += 256) lmax = fmaxf(lmax, xr[j]);
    red[t] = lmax; __syncthreads();
    for (int o = 128; o > 0; o >>= 1) { if (t < o) red[t] = fmaxf(red[t], red[t + o]); __syncthreads(); }
    float mx = red[0];
    __syncthreads();
    float ls = 0.f;
    for (int j = t; j < n; j += 256) { float e = expf(xr[j] - mx); xr[j] = e; ls += e; }
    red[t] = ls; __syncthreads();
    for (int o = 128; o > 0; o >>= 1) { if (t < o) red[t] += red[t + o]; __syncthreads(); }
    float inv = 1.0f / red[0];
    for (int j = t; j < n; j += 256) xr[j] *= inv;
}

__global__ void extract_cls_kernel(const float* __restrict__ t, float* __restrict__ cls) {
    int idx = blockIdx.x * blockDim.x + threadIdx.x;
    if (idx >= Bc * Dc) return;
    int b = idx / Dc, j = idx % Dc;
    cls[idx] = t[((long long)b * Sc) * Dc + j];
}

// ---------------- host helpers ----------------
static const int GEMM_SMEM = GS * 5120 * 4;   // 81920 bytes

static void run_gemm(const float* A, const float* Bm, const float* bias,
                     const float* res, float* C, int M, int N, int K,
                     int lda, int ldb, int ldc, int act, int rnd) {
    dim3 grid((N + 127) / 128, (M + 127) / 128, 1);
    mma_gemm_kernel<<<grid, 256, GEMM_SMEM>>>(A, Bm, bias, res, C, M, N, K, lda, ldb, ldc, act, rnd);
}

extern "C" void kernel_launch(void* const* d_in, const int* in_sizes, int n_in,
                              void* d_out, int out_size) {
    const float* x       = (const float*)d_in[0];
    const float* conv_w  = (const float*)d_in[1];
    const float* conv_b  = (const float*)d_in[2];
    const float* cls_tok = (const float*)d_in[3];
    const float* pos_emb = (const float*)d_in[4];
    const float* ln1_g   = (const float*)d_in[5];
    const float* ln1_b   = (const float*)d_in[6];
    const float* wqkv    = (const float*)d_in[7];
    const float* bqkv    = (const float*)d_in[8];
    const float* wmsa    = (const float*)d_in[9];
    const float* bmsa    = (const float*)d_in[10];
    const float* ln2_g   = (const float*)d_in[11];
    const float* ln2_b   = (const float*)d_in[12];
    const float* lnm_g   = (const float*)d_in[13];
    const float* lnm_b   = (const float*)d_in[14];
    const float* w1      = (const float*)d_in[15];
    const float* b1      = (const float*)d_in[16];
    const float* w2      = (const float*)d_in[17];
    const float* b2      = (const float*)d_in[18];
    const float* lnf_g   = (const float*)d_in[19];
    const float* lnf_b   = (const float*)d_in[20];
    const float* whead   = (const float*)d_in[21];
    const float* bhead   = (const float*)d_in[22];
    float* out = (float*)d_out;

    float *t_, *h_, *om_, *qkv_, *mb_, *col_, *wtq_, *cwt_, *cls_, *kT_;
    float *wmsar_, *w1r_, *w2r_, *whr_;
    cudaGetSymbolAddress((void**)&t_,  g_t);
    cudaGetSymbolAddress((void**)&h_,  g_h);
    cudaGetSymbolAddress((void**)&om_, g_om);
    cudaGetSymbolAddress((void**)&qkv_, g_qkv);
    cudaGetSymbolAddress((void**)&mb_, g_mbuf);
    cudaGetSymbolAddress((void**)&col_, g_col);
    cudaGetSymbolAddress((void**)&wtq_, g_wtqkv);
    cudaGetSymbolAddress((void**)&cwt_, g_cwt);
    cudaGetSymbolAddress((void**)&cls_, g_cls);
    cudaGetSymbolAddress((void**)&kT_, g_kT);
    cudaGetSymbolAddress((void**)&wmsar_, g_wmsar);
    cudaGetSymbolAddress((void**)&w1r_, g_w1r);
    cudaGetSymbolAddress((void**)&w2r_, g_w2r);
    cudaGetSymbolAddress((void**)&whr_, g_whr);

    cudaFuncSetAttribute(flash_kernel, cudaFuncAttributeMaxDynamicSharedMemorySize, 143360);
    cudaFuncSetAttribute(mma_gemm_kernel, cudaFuncAttributeMaxDynamicSharedMemorySize, GEMM_SMEM);

    // --- weight prep: round + transpose to [N][K] ---
    round_copy_kernel<<<(Dc * Dc + 255) / 256, 256>>>(conv_w, cwt_, (long long)Dc * Dc);
    {
        long long tot = (long long)Lc * 3 * Dc * Dc;
        transpose_wqkv_kernel<<<(int)((tot + 255) / 256), 256>>>(wqkv, wtq_);
    }
    {
        dim3 tb(32, 8);
        btrans_kernel<<<dim3(Dc / 32, Dc / 32, Lc), tb>>>(wmsa, wmsar_, Dc, Dc);
        btrans_kernel<<<dim3(Mc / 32, Dc / 32, Lc), tb>>>(w1, w1r_, Dc, Mc);
        btrans_kernel<<<dim3(Dc / 32, Mc / 32, Lc), tb>>>(w2, w2r_, Mc, Dc);
        btrans_kernel<<<dim3((NCc + 31) / 32, Dc / 32, 1), tb>>>(whead, whr_, Dc, NCc);
    }

    // --- patchify ---
    {
        long long tot = (long long)Bc * NP * Dc;
        im2col_kernel<<<(int)((tot + 255) / 256), 256>>>(x, col_);
    }
    run_gemm(col_, cwt_, conv_b, nullptr, h_, Bc * NP, Dc, Dc, Dc, Dc, Dc, 0, 0);
    {
        long long tot = (long long)Bc * Sc * Dc;
        embed_kernel<<<(int)((tot + 255) / 256), 256>>>(h_, cls_tok, pos_emb, t_);
    }

    // --- encoder layers ---
    for (int l = 0; l < Lc; l++) {
        layernorm_kernel<<<BS, 256>>>(t_, ln1_g + l * Dc, ln1_b + l * Dc, h_, BS);
        run_gemm(h_, wtq_ + (long long)l * 3 * Dc * Dc, bqkv + l * 3 * Dc, nullptr,
                 qkv_, BS, 3 * Dc, Dc, Dc, Dc, 3 * Dc, 0, 1);
        ktrans_kernel<<<dim3(KTW / 32, 2, Bc * Hc), dim3(32, 8)>>>(qkv_, kT_);
        flash_kernel<<<dim3((Sc + 127) / 128, Hc, Bc), 256, 143360>>>(qkv_, kT_, om_);
        run_gemm(om_, wmsar_ + (long long)l * Dc * Dc, bmsa + l * Dc, h_, t_,
                 BS, Dc, Dc, Dc, Dc, Dc, 0, 0);
        layernorm2_kernel<<<BS, 256>>>(t_, ln2_g + l * Dc, ln2_b + l * Dc,
                                       lnm_g + l * Dc, lnm_b + l * Dc, h_, BS);
        run_gemm(h_, w1r_ + (long long)l * Mc * Dc, b1 + l * Mc, nullptr, mb_,
                 BS, Mc, Dc, Dc, Dc, Mc, 1, 1);
        run_gemm(mb_, w2r_ + (long long)l * Dc * Mc, b2 + l * Dc, t_, t_,
                 BS, Dc, Mc, Mc, Mc, Dc, 0, 0);
    }

    // --- head ---
    extract_cls_kernel<<<(Bc * Dc + 255) / 256, 256>>>(t_, cls_);
    layernorm_kernel<<<Bc, 256>>>(cls_, lnf_g, lnf_b, cls_, Bc);
    run_gemm(cls_, whr_, bhead, nullptr, out, Bc, NCc, Dc, Dc, Dc, NCc, 0, 0);
    softmax_kernel<<<Bc, 256>>>(out, Bc, NCc);
}

// round 7
// speedup vs baseline: 1.1054x; 1.0010x over previous
#include <cuda_runtime.h>
#include <math.h>
#include <stdint.h>

// ---------------- dims ----------------
static const int Lc = 12, Hc = 12, Dc = 768, HDc = 64, Mc = 3072;
static const int IMGc = 384, Bc = 32, NCc = 1000;
static const int NP = 576;
static const int Sc = 577;
static const int BS = Bc * Sc;        // 18464
static const int GRID24 = 24;
static const int KTW = 640;
static const int GS = 4;              // gemm pipeline stages

// ---------------- scratch ----------------
__device__ float g_t[BS * Dc];
__device__ float g_h[BS * Dc];
__device__ float g_om[BS * Dc];
__device__ float g_qkv[BS * 3 * Dc];
__device__ float g_mbuf[BS * Mc];
__device__ float g_col[Bc * NP * Dc];
__device__ float g_wtqkv[Lc * 3 * Dc * Dc];   // [l][n=2304][k=768]
__device__ float g_cwt[Dc * Dc];              // conv_w rounded, already [n][k]
__device__ float g_cls[Bc * Dc];
__device__ float g_kT[(long long)Bc * Hc * HDc * KTW];
__device__ float g_wmsar[Lc * Dc * Dc];       // [l][d_out][d_in]
__device__ float g_w1r[Lc * Mc * Dc];         // [l][m][d]
__device__ float g_w2r[Lc * Dc * Mc];         // [l][d][m]
__device__ float g_whr[NCc * Dc];             // [nc][d]

// ---------------- tf32 helpers ----------------
__device__ __forceinline__ uint32_t f2tf(float f) {
    uint32_t u;
    asm("cvt.rna.tf32.f32 %0, %1;" : "=r"(u) : "f"(f));
    return u;
}
__device__ __forceinline__ float f2tf_f(float f) { return __uint_as_float(f2tf(f)); }

__device__ __forceinline__ void mma_tf32(float c[4], const uint32_t a[4], const uint32_t b[2]) {
    asm volatile(
        "mma.sync.aligned.m16n8k8.row.col.f32.tf32.tf32.f32 "
        "{%0,%1,%2,%3}, {%4,%5,%6,%7}, {%8,%9}, {%0,%1,%2,%3};\n"
        : "+f"(c[0]), "+f"(c[1]), "+f"(c[2]), "+f"(c[3])
        : "r"(a[0]), "r"(a[1]), "r"(a[2]), "r"(a[3]), "r"(b[0]), "r"(b[1]));
}

__device__ __forceinline__ void cp_async16(void* smem_dst, const void* gsrc, int sz) {
    unsigned sm = (unsigned)__cvta_generic_to_shared(smem_dst);
    asm volatile("cp.async.ca.shared.global [%0], [%1], 16, %2;\n" :: "r"(sm), "l"(gsrc), "r"(sz));
}

__device__ __forceinline__ void ldsm4(uint32_t r[4], const float* p) {
    unsigned a = (unsigned)__cvta_generic_to_shared(p);
    asm volatile("ldmatrix.sync.aligned.m8n8.x4.shared.b16 {%0,%1,%2,%3}, [%4];\n"
                 : "=r"(r[0]), "=r"(r[1]), "=r"(r[2]), "=r"(r[3]) : "r"(a));
}

// ---------------- dense tf32 GEMM: both operands K-major, ldmatrix frags ----------------
// C[M,N] = act( A[m][k] @ B[n][k]^T + bias + res ). B is pre-transposed weights.
// CTA 128x128, 8 warps (2x4) of 64x32, BK=16, GS-stage cp.async pipeline.
// dynamic smem: per stage: A[128][20] then B[128][20]  (5120 floats)
__global__ void __launch_bounds__(256, 2)
mma_gemm_kernel(const float* __restrict__ A, const float* __restrict__ Bm,
                const float* __restrict__ bias, const float* __restrict__ res,
                float* __restrict__ C,
                int M, int N, int K, int lda, int ldb, int ldc,
                int act, int rnd) {
    extern __shared__ float sm[];

    int t = threadIdx.x;
    int lane = t & 31, wid = t >> 5;
    int wm = wid >> 2, wn = wid & 3;          // 2 x 4 warps
    int g = lane >> 2, tig = lane & 3;
    int m0 = blockIdx.y * 128, n0 = blockIdx.x * 128;

    float acc[4][4][4] = {};
    int nk = K / 16;

    auto loadTile = [&](int k0, int s) {
        float* dstA = sm + s * 5120;
        float* dstB = dstA + 2560;
#pragma unroll
        for (int i = 0; i < 2; i++) {
            int c = t + i * 256;
            int m = c >> 2, kq = (c & 3) * 4;
            cp_async16(dstA + m * 20 + kq, A + (long long)(m0 + m) * lda + k0 + kq,
                       (m0 + m < M) ? 16 : 0);
        }
#pragma unroll
        for (int i = 0; i < 2; i++) {
            int c = t + i * 256;
            int n = c >> 2, kq = (c & 3) * 4;
            cp_async16(dstB + n * 20 + kq, Bm + (long long)(n0 + n) * ldb + k0 + kq,
                       (n0 + n < N) ? 16 : 0);
        }
    };

#pragma unroll
    for (int s = 0; s < GS - 1; s++) {
        loadTile(s * 16, s);
        asm volatile("cp.async.commit_group;\n");
    }

    int arow = wm * 64 + (lane & 15);
    int brow = wn * 32 + (lane & 15);
    int colb = 4 * (lane >> 4);               // 0 or 4

    for (int it = 0; it < nk; it++) {
        asm volatile("cp.async.wait_group %0;\n" :: "n"(GS - 2));
        __syncthreads();
        if (it + GS - 1 < nk) loadTile((it + GS - 1) * 16, (it + GS - 1) % GS);
        asm volatile("cp.async.commit_group;\n");

        int s = it % GS;
        const float* Ab = sm + s * 5120;
        const float* Bb = Ab + 2560;
#pragma unroll
        for (int ks = 0; ks < 2; ks++) {
            int kc = ks * 8 + colb;
            uint32_t af[4][4], bq[2][4];
#pragma unroll
            for (int mt = 0; mt < 4; mt++)
                ldsm4(af[mt], Ab + (arow + mt * 16) * 20 + kc);
#pragma unroll
            for (int nh = 0; nh < 2; nh++)
                ldsm4(bq[nh], Bb + (brow + nh * 16) * 20 + kc);
#pragma unroll
            for (int mt = 0; mt < 4; mt++)
#pragma unroll
                for (int nt = 0; nt < 4; nt++) {
                    uint32_t b2[2] = { bq[nt >> 1][nt & 1], bq[nt >> 1][2 + (nt & 1)] };
                    mma_tf32(acc[mt][nt], af[mt], b2);
                }
        }
    }

    // epilogue
#pragma unroll
    for (int mt = 0; mt < 4; mt++) {
#pragma unroll
        for (int nt = 0; nt < 4; nt++) {
            int row = m0 + wm * 64 + mt * 16 + g;
            int col = n0 + wn * 32 + nt * 8 + tig * 2;
#pragma unroll
            for (int cc = 0; cc < 4; cc++) {
                int m = row + (cc >> 1) * 8;
                int n = col + (cc & 1);
                if (m >= M || n >= N) continue;
                float v = acc[mt][nt][cc];
                if (bias) v += bias[n];
                if (res) v += res[(long long)m * ldc + n];
                if (act == 1) v = 0.5f * v * (1.0f + erff(v * 0.7071067811865476f));
                if (rnd) v = f2tf_f(v);
                C[(long long)m * ldc + n] = v;
            }
        }
    }
}

// ---------------- fused flash attention (unchanged) ----------------
__global__ void __launch_bounds__(256)
flash_kernel(const float* __restrict__ qkv, const float* __restrict__ kT,
             float* __restrict__ om) {
    extern __shared__ float smf[];
    float* Qs = smf;               // [128][68]
    float* Ps = smf + 8704;        // [8][16][68]
    float* Ks = smf + 17408;       // [2][64][72]
    float* Vs = smf + 26624;       // [2][64][72]

    int qt = blockIdx.x, h = blockIdx.y, b = blockIdx.z;
    int t = threadIdx.x, lane = t & 31, w = t >> 5, g = lane >> 2, tig = lane & 3;
    const float* qb = qkv + (long long)b * Sc * 2304 + h * 192;
    const float* kb = kT + ((long long)(b * Hc + h)) * HDc * KTW;

#pragma unroll
    for (int i = 0; i < 8; i++) {
        int idx = t + i * 256;
        int row = idx >> 4, c4 = (idx & 15) * 4;
        int gr = qt * 128 + row;
        cp_async16(&Qs[row * 68 + c4], qb + (long long)gr * 2304 + c4, gr < Sc ? 16 : 0);
    }
    auto issueK = [&](int kt_, int buf) {
#pragma unroll
        for (int i = 0; i < 4; i++) {
            int idx = t + i * 256;
            int hd = idx >> 4, c4 = (idx & 15) * 4;
            cp_async16(&Ks[(buf * 64 + hd) * 72 + c4], kb + hd * KTW + kt_ * 64 + c4, 16);
        }
    };
    auto issueV = [&](int kt_, int buf) {
#pragma unroll
        for (int i = 0; i < 4; i++) {
            int idx = t + i * 256;
            int row = idx >> 4, c4 = (idx & 15) * 4;
            int gk = kt_ * 64 + row;
            cp_async16(&Vs[(buf * 64 + row) * 72 + c4],
                       qb + (long long)gk * 2304 + 128 + c4, gk < Sc ? 16 : 0);
        }
    };
    issueK(0, 0);
    issueV(0, 0);
    asm volatile("cp.async.commit_group;\n");

    float accO[8][4] = {};
    float mr0 = -1e30f, mr1 = -1e30f, lr0 = 0.f, lr1 = 0.f;
    float* Pw = Ps + w * 16 * 68;
    const int nt = (Sc + 63) / 64;

    for (int kt_ = 0; kt_ < nt; kt_++) {
        int buf = kt_ & 1;
        __syncthreads();
        if (kt_ + 1 < nt) { issueK(kt_ + 1, buf ^ 1); issueV(kt_ + 1, buf ^ 1); }
        asm volatile("cp.async.commit_group;\n");
        asm volatile("cp.async.wait_group 1;\n");
        __syncthreads();

        float s[8][4] = {};
        const float* Kb = Ks + buf * 64 * 72;
#pragma unroll
        for (int ks = 0; ks < 8; ks++) {
            int kk = ks * 8;
            uint32_t af[4];
            af[0] = __float_as_uint(Qs[(w * 16 + g) * 68 + kk + tig]);
            af[1] = __float_as_uint(Qs[(w * 16 + g + 8) * 68 + kk + tig]);
            af[2] = __float_as_uint(Qs[(w * 16 + g) * 68 + kk + tig + 4]);
            af[3] = __float_as_uint(Qs[(w * 16 + g + 8) * 68 + kk + tig + 4]);
#pragma unroll
            for (int nf = 0; nf < 8; nf++) {
                uint32_t bf[2];
                bf[0] = __float_as_uint(Kb[(kk + tig) * 72 + nf * 8 + g]);
                bf[1] = __float_as_uint(Kb[(kk + tig + 4) * 72 + nf * 8 + g]);
                mma_tf32(s[nf], af, bf);
            }
        }
        float rm0 = -1e30f, rm1 = -1e30f;
#pragma unroll
        for (int nf = 0; nf < 8; nf++) {
#pragma unroll
            for (int cc = 0; cc < 4; cc++) {
                int col = kt_ * 64 + nf * 8 + tig * 2 + (cc & 1);
                float v = s[nf][cc] * 0.125f;
                v = (col < Sc) ? v : -1e30f;
                s[nf][cc] = v;
                if (cc < 2) rm0 = fmaxf(rm0, v); else rm1 = fmaxf(rm1, v);
            }
        }
        rm0 = fmaxf(rm0, __shfl_xor_sync(0xffffffffu, rm0, 1));
        rm0 = fmaxf(rm0, __shfl_xor_sync(0xffffffffu, rm0, 2));
        rm1 = fmaxf(rm1, __shfl_xor_sync(0xffffffffu, rm1, 1));
        rm1 = fmaxf(rm1, __shfl_xor_sync(0xffffffffu, rm1, 2));
        float nm0 = fmaxf(mr0, rm0), nm1 = fmaxf(mr1, rm1);
        float cor0 = __expf(mr0 - nm0), cor1 = __expf(mr1 - nm1);
        float rs0 = 0.f, rs1 = 0.f;
#pragma unroll
        for (int nf = 0; nf < 8; nf++) {
            int colb = nf * 8 + tig * 2;
            float p0 = __expf(s[nf][0] - nm0);
            float p1 = __expf(s[nf][1] - nm0);
            float p2 = __expf(s[nf][2] - nm1);
            float p3 = __expf(s[nf][3] - nm1);
            rs0 += p0 + p1; rs1 += p2 + p3;
            Pw[g * 68 + colb]       = f2tf_f(p0);
            Pw[g * 68 + colb + 1]   = f2tf_f(p1);
            Pw[(g + 8) * 68 + colb]     = f2tf_f(p2);
            Pw[(g + 8) * 68 + colb + 1] = f2tf_f(p3);
        }
        rs0 += __shfl_xor_sync(0xffffffffu, rs0, 1);
        rs0 += __shfl_xor_sync(0xffffffffu, rs0, 2);
        rs1 += __shfl_xor_sync(0xffffffffu, rs1, 1);
        rs1 += __shfl_xor_sync(0xffffffffu, rs1, 2);
        lr0 = lr0 * cor0 + rs0;
        lr1 = lr1 * cor1 + rs1;
        mr0 = nm0; mr1 = nm1;
#pragma unroll
        for (int nf = 0; nf < 8; nf++) {
            accO[nf][0] *= cor0; accO[nf][1] *= cor0;
            accO[nf][2] *= cor1; accO[nf][3] *= cor1;
        }
        __syncwarp();
        const float* Vb = Vs + buf * 64 * 72;
#pragma unroll
        for (int ks = 0; ks < 8; ks++) {
            int kk = ks * 8;
            uint32_t af[4];
            af[0] = __float_as_uint(Pw[g * 68 + kk + tig]);
            af[1] = __float_as_uint(Pw[(g + 8) * 68 + kk + tig]);
            af[2] = __float_as_uint(Pw[g * 68 + kk + tig + 4]);
            af[3] = __float_as_uint(Pw[(g + 8) * 68 + kk + tig + 4]);
#pragma unroll
            for (int nf = 0; nf < 8; nf++) {
                uint32_t bf[2];
                bf[0] = __float_as_uint(Vb[(kk + tig) * 72 + nf * 8 + g]);
                bf[1] = __float_as_uint(Vb[(kk + tig + 4) * 72 + nf * 8 + g]);
                mma_tf32(accO[nf], af, bf);
            }
        }
    }

    float inv0 = 1.0f / lr0, inv1 = 1.0f / lr1;
    int r0 = qt * 128 + w * 16 + g;
    int r1 = r0 + 8;
#pragma unroll
    for (int nf = 0; nf < 8; nf++) {
        int colb = nf * 8 + tig * 2;
        if (r0 < Sc) {
            om[((long long)b * Sc + r0) * Dc + h * 64 + colb]     = f2tf_f(accO[nf][0] * inv0);
            om[((long long)b * Sc + r0) * Dc + h * 64 + colb + 1] = f2tf_f(accO[nf][1] * inv0);
        }
        if (r1 < Sc) {
            om[((long long)b * Sc + r1) * Dc + h * 64 + colb]     = f2tf_f(accO[nf][2] * inv1);
            om[((long long)b * Sc + r1) * Dc + h * 64 + colb + 1] = f2tf_f(accO[nf][3] * inv1);
        }
    }
}

// ---------------- K transpose ----------------
__global__ void ktrans_kernel(const float* __restrict__ qkv, float* __restrict__ kT) {
    __shared__ float tile[32][33];
    int ktile = blockIdx.x;
    int hdt = blockIdx.y;
    int bh = blockIdx.z;
    int b = bh / Hc, h = bh % Hc;
    int tx = threadIdx.x, ty = threadIdx.y;
#pragma unroll
    for (int j = 0; j < 4; j++) {
        int key = ktile * 32 + ty + j * 8;
        int hd = hdt * 32 + tx;
        float v = 0.f;
        if (key < Sc) v = qkv[((long long)b * Sc + key) * 2304 + h * 192 + 64 + hd];
        tile[ty + j * 8][tx] = v;
    }
    __syncthreads();
#pragma unroll
    for (int j = 0; j < 4; j++) {
        int hd = hdt * 32 + ty + j * 8;
        int key = ktile * 32 + tx;
        kT[((long long)bh * HDc + hd) * KTW + key] = tile[tx][ty + j * 8];
    }
}

// ---------------- aux kernels ----------------
__global__ void im2col_kernel(const float* __restrict__ x, float* __restrict__ col) {
    long long idx = (long long)blockIdx.x * blockDim.x + threadIdx.x;
    long long total = (long long)Bc * NP * Dc;
    if (idx >= total) return;
    int k = (int)(idx % Dc);
    int rem = (int)(idx / Dc);
    int p = rem % NP;
    int b = rem / NP;
    int ph = p / GRID24, pw = p % GRID24;
    int ci = k / 256, k2 = k % 256;
    int kh = k2 / 16, kw = k2 % 16;
    col[idx] = f2tf_f(x[(((long long)b * 3 + ci) * IMGc + ph * 16 + kh) * IMGc + pw * 16 + kw]);
}

// transpose wqkv to [l][n=2304][k=768], rounded
__global__ void transpose_wqkv_kernel(const float* __restrict__ w, float* __restrict__ wt) {
    long long idx = (long long)blockIdx.x * blockDim.x + threadIdx.x;
    long long total = (long long)Lc * 3 * Dc * Dc;
    if (idx >= total) return;
    int d = (int)(idx % Dc);
    int rem = (int)(idx / Dc);
    int n = rem % (3 * Dc);
    int l = rem / (3 * Dc);
    int h = n / 192, e = n % 192;
    wt[idx] = f2tf_f(w[(((long long)l * Hc + h) * Dc + d) * 192 + e]);
}

// generic batched transpose with tf32 round: out[l][c][r] = round(in[l][r][c])
__global__ void btrans_kernel(const float* __restrict__ in, float* __restrict__ out,
                              int R, int Cn) {
    __shared__ float tile[32][33];
    int ct = blockIdx.x, rt = blockIdx.y, l = blockIdx.z;
    const float* inl = in + (long long)l * R * Cn;
    float* outl = out + (long long)l * R * Cn;
    int tx = threadIdx.x, ty = threadIdx.y;   // 32 x 8
#pragma unroll
    for (int j = 0; j < 4; j++) {
        int r = rt * 32 + ty + j * 8;
        int c = ct * 32 + tx;
        tile[ty + j * 8][tx] = (r < R && c < Cn) ? inl[(long long)r * Cn + c] : 0.f;
    }
    __syncthreads();
#pragma unroll
    for (int j = 0; j < 4; j++) {
        int c = ct * 32 + ty + j * 8;
        int r = rt * 32 + tx;
        if (c < Cn && r < R)
            outl[(long long)c * R + r] = f2tf_f(tile[tx][ty + j * 8]);
    }
}

__global__ void round_copy_kernel(const float* __restrict__ w, float* __restrict__ o, long long n) {
    long long i = (long long)blockIdx.x * blockDim.x + threadIdx.x;
    if (i < n) o[i] = f2tf_f(w[i]);
}

__global__ void embed_kernel(const float* __restrict__ pout, const float* __restrict__ cls,
                             const float* __restrict__ pos, float* __restrict__ t) {
    long long idx = (long long)blockIdx.x * blockDim.x + threadIdx.x;
    long long total = (long long)Bc * Sc * Dc;
    if (idx >= total) return;
    int j = (int)(idx % Dc);
    int rem = (int)(idx / Dc);
    int r = rem % Sc;
    int b = rem / Sc;
    float v;
    if (r == 0) {
        v = cls[j];
    } else {
        int i = (r - 1) * Dc + j;
        int c = i / NP, p = i % NP;
        v = pout[((long long)b * NP + p) * Dc + c];
    }
    t[idx] = v + pos[r * Dc + j];
}

__global__ void layernorm_kernel(const float* __restrict__ x, const float* __restrict__ g,
                                 const float* __restrict__ b, float* __restrict__ y, int rows) {
    __shared__ float red[256];
    int row = blockIdx.x;
    if (row >= rows) return;
    int t = threadIdx.x;
    const float* xr = x + (long long)row * Dc;
    float v[3];
    float s = 0.f;
#pragma unroll
    for (int i = 0; i < 3; i++) { v[i] = xr[t + i * 256]; s += v[i]; }
    red[t] = s; __syncthreads();
    for (int o = 128; o > 0; o >>= 1) { if (t < o) red[t] += red[t + o]; __syncthreads(); }
    float mu = red[0] / Dc;
    __syncthreads();
    float s2 = 0.f;
#pragma unroll
    for (int i = 0; i < 3; i++) { float d = v[i] - mu; s2 += d * d; }
    red[t] = s2; __syncthreads();
    for (int o = 128; o > 0; o >>= 1) { if (t < o) red[t] += red[t + o]; __syncthreads(); }
    float rstd = rsqrtf(red[0] / Dc + 1e-5f);
    float* yr = y + (long long)row * Dc;
#pragma unroll
    for (int i = 0; i < 3; i++) {
        int j = t + i * 256;
        yr[j] = f2tf_f((v[i] - mu) * rstd * g[j] + b[j]);
    }
}

// fused double layernorm
__global__ void layernorm2_kernel(const float* __restrict__ x,
                                  const float* __restrict__ g1, const float* __restrict__ b1,
                                  const float* __restrict__ g2, const float* __restrict__ b2,
                                  float* __restrict__ y, int rows) {
    __shared__ float red[256];
    int row = blockIdx.x;
    if (row >= rows) return;
    int t = threadIdx.x;
    const float* xr = x + (long long)row * Dc;
    float v[3];
    float s = 0.f;
#pragma unroll
    for (int i = 0; i < 3; i++) { v[i] = xr[t + i * 256]; s += v[i]; }
    red[t] = s; __syncthreads();
    for (int o = 128; o > 0; o >>= 1) { if (t < o) red[t] += red[t + o]; __syncthreads(); }
    float mu = red[0] / Dc;
    __syncthreads();
    float s2 = 0.f;
#pragma unroll
    for (int i = 0; i < 3; i++) { float d = v[i] - mu; s2 += d * d; }
    red[t] = s2; __syncthreads();
    for (int o = 128; o > 0; o >>= 1) { if (t < o) red[t] += red[t + o]; __syncthreads(); }
    float rstd = rsqrtf(red[0] / Dc + 1e-5f);
    __syncthreads();
    s = 0.f;
#pragma unroll
    for (int i = 0; i < 3; i++) {
        int j = t + i * 256;
        v[i] = (v[i] - mu) * rstd * g1[j] + b1[j];
        s += v[i];
    }
    red[t] = s; __syncthreads();
    for (int o = 128; o > 0; o >>= 1) { if (t < o) red[t] += red[t + o]; __syncthreads(); }
    mu = red[0] / Dc;
    __syncthreads();
    s2 = 0.f;
#pragma unroll
    for (int i = 0; i < 3; i++) { float d = v[i] - mu; s2 += d * d; }
    red[t] = s2; __syncthreads();
    for (int o = 128; o > 0; o >>= 1) { if (t < o) red[t] += red[t + o]; __syncthreads(); }
    rstd = rsqrtf(red[0] / Dc + 1e-5f);
    float* yr = y + (long long)row * Dc;
#pragma unroll
    for (int i = 0; i < 3; i++) {
        int j = t + i * 256;
        yr[j] = f2tf_f((v[i] - mu) * rstd * g2[j] + b2[j]);
    }
}

__global__ void softmax_kernel(float* __restrict__ x, long long rows, int n) {
    __shared__ float red[256];
    long long row = blockIdx.x;
    if (row >= rows) return;
    int t = threadIdx.x;
    float* xr = x + row * n;
    float lmax = -1e30f;
    for (int j = t; j < n; j += 256) lmax = fmaxf(lmax, xr[j]);
    red[t] = lmax; __syncthreads();
    for (int o = 128; o > 0; o >>= 1) { if (t < o) red[t] = fmaxf(red[t], red[t + o]); __syncthreads(); }
    float mx = red[0];
    __syncthreads();
    float ls = 0.f;
    for (int j = t; j < n; j += 256) { float e = expf(xr[j] - mx); xr[j] = e; ls += e; }
    red[t] = ls; __syncthreads();
    for (int o = 128; o > 0; o >>= 1) { if (t < o) red[t] += red[t + o]; __syncthreads(); }
    float inv = 1.0f / red[0];
    for (int j = t; j < n; j += 256) xr[j] *= inv;
}

__global__ void extract_cls_kernel(const float* __restrict__ t, float* __restrict__ cls) {
    int idx = blockIdx.x * blockDim.x + threadIdx.x;
    if (idx >= Bc * Dc) return;
    int b = idx / Dc, j = idx % Dc;
    cls[idx] = t[((long long)b * Sc) * Dc + j];
}

// ---------------- host helpers ----------------
static const int GEMM_SMEM = GS * 5120 * 4;   // 81920 bytes

static void run_gemm(const float* A, const float* Bm, const float* bias,
                     const float* res, float* C, int M, int N, int K,
                     int lda, int ldb, int ldc, int act, int rnd) {
    dim3 grid((N + 127) / 128, (M + 127) / 128, 1);
    mma_gemm_kernel<<<grid, 256, GEMM_SMEM>>>(A, Bm, bias, res, C, M, N, K, lda, ldb, ldc, act, rnd);
}

extern "C" void kernel_launch(void* const* d_in, const int* in_sizes, int n_in,
                              void* d_out, int out_size) {
    const float* x       = (const float*)d_in[0];
    const float* conv_w  = (const float*)d_in[1];
    const float* conv_b  = (const float*)d_in[2];
    const float* cls_tok = (const float*)d_in[3];
    const float* pos_emb = (const float*)d_in[4];
    const float* ln1_g   = (const float*)d_in[5];
    const float* ln1_b   = (const float*)d_in[6];
    const float* wqkv    = (const float*)d_in[7];
    const float* bqkv    = (const float*)d_in[8];
    const float* wmsa    = (const float*)d_in[9];
    const float* bmsa    = (const float*)d_in[10];
    const float* ln2_g   = (const float*)d_in[11];
    const float* ln2_b   = (const float*)d_in[12];
    const float* lnm_g   = (const float*)d_in[13];
    const float* lnm_b   = (const float*)d_in[14];
    const float* w1      = (const float*)d_in[15];
    const float* b1      = (const float*)d_in[16];
    const float* w2      = (const float*)d_in[17];
    const float* b2      = (const float*)d_in[18];
    const float* lnf_g   = (const float*)d_in[19];
    const float* lnf_b   = (const float*)d_in[20];
    const float* whead   = (const float*)d_in[21];
    const float* bhead   = (const float*)d_in[22];
    float* out = (float*)d_out;

    float *t_, *h_, *om_, *qkv_, *mb_, *col_, *wtq_, *cwt_, *cls_, *kT_;
    float *wmsar_, *w1r_, *w2r_, *whr_;
    cudaGetSymbolAddress((void**)&t_,  g_t);
    cudaGetSymbolAddress((void**)&h_,  g_h);
    cudaGetSymbolAddress((void**)&om_, g_om);
    cudaGetSymbolAddress((void**)&qkv_, g_qkv);
    cudaGetSymbolAddress((void**)&mb_, g_mbuf);
    cudaGetSymbolAddress((void**)&col_, g_col);
    cudaGetSymbolAddress((void**)&wtq_, g_wtqkv);
    cudaGetSymbolAddress((void**)&cwt_, g_cwt);
    cudaGetSymbolAddress((void**)&cls_, g_cls);
    cudaGetSymbolAddress((void**)&kT_, g_kT);
    cudaGetSymbolAddress((void**)&wmsar_, g_wmsar);
    cudaGetSymbolAddress((void**)&w1r_, g_w1r);
    cudaGetSymbolAddress((void**)&w2r_, g_w2r);
    cudaGetSymbolAddress((void**)&whr_, g_whr);

    cudaFuncSetAttribute(flash_kernel, cudaFuncAttributeMaxDynamicSharedMemorySize, 143360);
    cudaFuncSetAttribute(mma_gemm_kernel, cudaFuncAttributeMaxDynamicSharedMemorySize, GEMM_SMEM);

    // --- weight prep: round + transpose to [N][K] ---
    round_copy_kernel<<<(Dc * Dc + 255) / 256, 256>>>(conv_w, cwt_, (long long)Dc * Dc);
    {
        long long tot = (long long)Lc * 3 * Dc * Dc;
        transpose_wqkv_kernel<<<(int)((tot + 255) / 256), 256>>>(wqkv, wtq_);
    }
    {
        dim3 tb(32, 8);
        btrans_kernel<<<dim3(Dc / 32, Dc / 32, Lc), tb>>>(wmsa, wmsar_, Dc, Dc);
        btrans_kernel<<<dim3(Mc / 32, Dc / 32, Lc), tb>>>(w1, w1r_, Dc, Mc);
        btrans_kernel<<<dim3(Dc / 32, Mc / 32, Lc), tb>>>(w2, w2r_, Mc, Dc);
        btrans_kernel<<<dim3((NCc + 31) / 32, Dc / 32, 1), tb>>>(whead, whr_, Dc, NCc);
    }

    // --- patchify ---
    {
        long long tot = (long long)Bc * NP * Dc;
        im2col_kernel<<<(int)((tot + 255) / 256), 256>>>(x, col_);
    }
    run_gemm(col_, cwt_, conv_b, nullptr, h_, Bc * NP, Dc, Dc, Dc, Dc, Dc, 0, 0);
    {
        long long tot = (long long)Bc * Sc * Dc;
        embed_kernel<<<(int)((tot + 255) / 256), 256>>>(h_, cls_tok, pos_emb, t_);
    }

    // --- encoder layers ---
    for (int l = 0; l < Lc; l++) {
        layernorm_kernel<<<BS, 256>>>(t_, ln1_g + l * Dc, ln1_b + l * Dc, h_, BS);
        run_gemm(h_, wtq_ + (long long)l * 3 * Dc * Dc, bqkv + l * 3 * Dc, nullptr,
                 qkv_, BS, 3 * Dc, Dc, Dc, Dc, 3 * Dc, 0, 1);
        ktrans_kernel<<<dim3(KTW / 32, 2, Bc * Hc), dim3(32, 8)>>>(qkv_, kT_);
        flash_kernel<<<dim3((Sc + 127) / 128, Hc, Bc), 256, 143360>>>(qkv_, kT_, om_);
        run_gemm(om_, wmsar_ + (long long)l * Dc * Dc, bmsa + l * Dc, h_, t_,
                 BS, Dc, Dc, Dc, Dc, Dc, 0, 0);
        layernorm2_kernel<<<BS, 256>>>(t_, ln2_g + l * Dc, ln2_b + l * Dc,
                                       lnm_g + l * Dc, lnm_b + l * Dc, h_, BS);
        run_gemm(h_, w1r_ + (long long)l * Mc * Dc, b1 + l * Mc, nullptr, mb_,
                 BS, Mc, Dc, Dc, Dc, Mc, 1, 1);
        run_gemm(mb_, w2r_ + (long long)l * Dc * Mc, b2 + l * Dc, t_, t_,
                 BS, Dc, Mc, Mc, Mc, Dc, 0, 0);
    }

    // --- head ---
    extract_cls_kernel<<<(Bc * Dc + 255) / 256, 256>>>(t_, cls_);
    layernorm_kernel<<<Bc, 256>>>(cls_, lnf_g, lnf_b, cls_, Bc);
    run_gemm(cls_, whr_, bhead, nullptr, out, Bc, NCc, Dc, Dc, Dc, NCc, 0, 0);
    softmax_kernel<<<Bc, 256>>>(out, Bc, NCc);
}

// round 9
// speedup vs baseline: 1.5714x; 1.4216x over previous
#include <cuda_runtime.h>
#include <cuda_fp16.h>
#include <math.h>
#include <stdint.h>

// ---------------- dims ----------------
static const int Lc = 12, Hc = 12, Dc = 768, HDc = 64, Mc = 3072;
static const int IMGc = 384, Bc = 32, NCc = 1000;
static const int NP = 576;
static const int Sc = 577;
static const int BS = Bc * Sc;        // 18464
static const int GRID24 = 24;
static const int KTW = 640;
static const int GS = 4;              // gemm pipeline stages

// ---------------- scratch ----------------
__device__ float g_t[BS * Dc];                 // residual (fp32)
__device__ float g_h[BS * Dc];                 // ln1 out fp32 (msa residual)
__device__ float g_qkv[BS * 3 * Dc];           // fp32 (flash input)
__device__ float g_kT[(long long)Bc * Hc * HDc * KTW];
__device__ float g_cls[Bc * Dc];
// fp16 GEMM operands
__device__ __half g_h2[BS * Dc];               // ln out (act input)
__device__ __half g_om2[BS * Dc];              // flash out
__device__ __half g_mb2[(long long)BS * Mc];   // mlp intermediate
__device__ __half g_col2[Bc * NP * Dc];
__device__ __half g_cls2[Bc * Dc];
__device__ __half g_wq2[(long long)Lc * 3 * Dc * Dc];  // [l][n=2304][k=768]
__device__ __half g_cw2[Dc * Dc];                      // [n][k]
__device__ __half g_wm2[(long long)Lc * Dc * Dc];
__device__ __half g_w12[(long long)Lc * Mc * Dc];
__device__ __half g_w22[(long long)Lc * Dc * Mc];
__device__ __half g_wh2[NCc * Dc];

// ---------------- helpers ----------------
__device__ __forceinline__ uint32_t f2tf(float f) {
    uint32_t u;
    asm("cvt.rna.tf32.f32 %0, %1;" : "=r"(u) : "f"(f));
    return u;
}
__device__ __forceinline__ float f2tf_f(float f) { return __uint_as_float(f2tf(f)); }

__device__ __forceinline__ void mma_tf32(float c[4], const uint32_t a[4], const uint32_t b[2]) {
    asm volatile(
        "mma.sync.aligned.m16n8k8.row.col.f32.tf32.tf32.f32 "
        "{%0,%1,%2,%3}, {%4,%5,%6,%7}, {%8,%9}, {%0,%1,%2,%3};\n"
        : "+f"(c[0]), "+f"(c[1]), "+f"(c[2]), "+f"(c[3])
        : "r"(a[0]), "r"(a[1]), "r"(a[2]), "r"(a[3]), "r"(b[0]), "r"(b[1]));
}

__device__ __forceinline__ void mma_f16(float c[4], const uint32_t a[4], const uint32_t b[2]) {
    asm volatile(
        "mma.sync.aligned.m16n8k16.row.col.f32.f16.f16.f32 "
        "{%0,%1,%2,%3}, {%4,%5,%6,%7}, {%8,%9}, {%0,%1,%2,%3};\n"
        : "+f"(c[0]), "+f"(c[1]), "+f"(c[2]), "+f"(c[3])
        : "r"(a[0]), "r"(a[1]), "r"(a[2]), "r"(a[3]), "r"(b[0]), "r"(b[1]));
}

__device__ __forceinline__ void cp_async16(void* smem_dst, const void* gsrc, int sz) {
    unsigned sm = (unsigned)__cvta_generic_to_shared(smem_dst);
    asm volatile("cp.async.ca.shared.global [%0], [%1], 16, %2;\n" :: "r"(sm), "l"(gsrc), "r"(sz));
}

__device__ __forceinline__ void ldsm4h(uint32_t r[4], const __half* p) {
    unsigned a = (unsigned)__cvta_generic_to_shared(p);
    asm volatile("ldmatrix.sync.aligned.m8n8.x4.shared.b16 {%0,%1,%2,%3}, [%4];\n"
                 : "=r"(r[0]), "=r"(r[1]), "=r"(r[2]), "=r"(r[3]) : "r"(a));
}
__device__ __forceinline__ void ldsm4f(uint32_t r[4], const float* p) {
    unsigned a = (unsigned)__cvta_generic_to_shared(p);
    asm volatile("ldmatrix.sync.aligned.m8n8.x4.shared.b16 {%0,%1,%2,%3}, [%4];\n"
                 : "=r"(r[0]), "=r"(r[1]), "=r"(r[2]), "=r"(r[3]) : "r"(a));
}

// ---------------- fp16 tensor GEMM ----------------
// C = act(A[m][k] @ B[n][k]^T + bias [+res]); A,B fp16 K-major. acc fp32.
// CTA 128x128, 8 warps (2x4) 64x32, BK=32 halves, 4-stage cp.async.
// smem per stage: A 128x40 halves + B 128x40 halves (pad row=80B).
static const int HROW = 40;                      // halves per row (32 + 8 pad)
static const int HSTG = 128 * HROW;              // halves per operand per stage
static const int GEMM_SMEM = GS * 2 * HSTG * 2;  // bytes = 81920

__global__ void __launch_bounds__(256, 2)
hgemm_kernel(const __half* __restrict__ A, const __half* __restrict__ Bm,
             const float* __restrict__ bias, const float* __restrict__ res,
             float* __restrict__ Cf, __half* __restrict__ C2,
             int M, int N, int K, int ldc, int act, int rnd) {
    extern __shared__ __half smh[];

    int t = threadIdx.x;
    int lane = t & 31, wid = t >> 5;
    int wm = wid >> 2, wn = wid & 3;          // 2 x 4 warps
    int g = lane >> 2, tig = lane & 3;
    int m0 = blockIdx.y * 128, n0 = blockIdx.x * 128;

    float acc[4][4][4] = {};
    int nk = K / 32;

    auto loadTile = [&](int k0, int s) {
        __half* dstA = smh + s * 2 * HSTG;
        __half* dstB = dstA + HSTG;
#pragma unroll
        for (int i = 0; i < 2; i++) {
            int c = t + i * 256;
            int r = c >> 2, sg = (c & 3) * 8;
            cp_async16(dstA + r * HROW + sg, A + (long long)(m0 + r) * K + k0 + sg,
                       (m0 + r < M) ? 16 : 0);
        }
#pragma unroll
        for (int i = 0; i < 2; i++) {
            int c = t + i * 256;
            int r = c >> 2, sg = (c & 3) * 8;
            cp_async16(dstB + r * HROW + sg, Bm + (long long)(n0 + r) * K + k0 + sg,
                       (n0 + r < N) ? 16 : 0);
        }
    };

#pragma unroll
    for (int s = 0; s < GS - 1; s++) {
        loadTile(s * 32, s);
        asm volatile("cp.async.commit_group;\n");
    }

    // ldmatrix lane->address precompute
    int a_row = wm * 64 + (lane & 15);
    int a_cofs = (lane >> 4) << 3;                 // 0 or 8 halves
    int b_row = wn * 32 + ((lane >> 4) << 3) + (lane & 7);
    int b_cofs = ((lane >> 3) & 1) << 3;           // 0 or 8 halves

    for (int it = 0; it < nk; it++) {
        asm volatile("cp.async.wait_group %0;\n" :: "n"(GS - 2));
        __syncthreads();
        if (it + GS - 1 < nk) loadTile((it + GS - 1) * 32, (it + GS - 1) % GS);
        asm volatile("cp.async.commit_group;\n");

        const __half* Ab = smh + (it % GS) * 2 * HSTG;
        const __half* Bb = Ab + HSTG;
#pragma unroll
        for (int ks = 0; ks < 2; ks++) {
            int kc = ks * 16;
            uint32_t af[4][4], bq[2][4];
#pragma unroll
            for (int mt = 0; mt < 4; mt++)
                ldsm4h(af[mt], Ab + (a_row + mt * 16) * HROW + kc + a_cofs);
#pragma unroll
            for (int nb = 0; nb < 2; nb++)
                ldsm4h(bq[nb], Bb + (b_row + nb * 16) * HROW + kc + b_cofs);
#pragma unroll
            for (int mt = 0; mt < 4; mt++)
#pragma unroll
                for (int nt = 0; nt < 4; nt++) {
                    uint32_t b2[2] = { bq[nt >> 1][(nt & 1) * 2], bq[nt >> 1][(nt & 1) * 2 + 1] };
                    mma_f16(acc[mt][nt], af[mt], b2);
                }
        }
    }

    // epilogue
#pragma unroll
    for (int mt = 0; mt < 4; mt++) {
#pragma unroll
        for (int nt = 0; nt < 4; nt++) {
            int row = m0 + wm * 64 + mt * 16 + g;
            int col = n0 + wn * 32 + nt * 8 + tig * 2;
#pragma unroll
            for (int cc = 0; cc < 4; cc++) {
                int m = row + (cc >> 1) * 8;
                int n = col + (cc & 1);
                if (m >= M || n >= N) continue;
                float v = acc[mt][nt][cc];
                if (bias) v += bias[n];
                if (res) v += res[(long long)m * ldc + n];
                if (act == 1) v = 0.5f * v * (1.0f + erff(v * 0.7071067811865476f));
                if (Cf) Cf[(long long)m * ldc + n] = rnd ? f2tf_f(v) : v;
                if (C2) C2[(long long)m * ldc + n] = __float2half(v);
            }
        }
    }
}

// ---------------- fused flash attention (fp32 in, fp16 out) ----------------
__global__ void __launch_bounds__(256)
flash_kernel(const float* __restrict__ qkv, const float* __restrict__ kT,
             __half* __restrict__ om2) {
    extern __shared__ float smf[];
    float* Qs = smf;               // [128][68]
    float* Ps = smf + 8704;        // [8][16][68]
    float* Ks = smf + 17408;       // [2][64][72]
    float* Vs = smf + 26624;       // [2][64][72]

    int qt = blockIdx.x, h = blockIdx.y, b = blockIdx.z;
    int t = threadIdx.x, lane = t & 31, w = t >> 5, g = lane >> 2, tig = lane & 3;
    const float* qb = qkv + (long long)b * Sc * 2304 + h * 192;
    const float* kb = kT + ((long long)(b * Hc + h)) * HDc * KTW;

#pragma unroll
    for (int i = 0; i < 8; i++) {
        int idx = t + i * 256;
        int row = idx >> 4, c4 = (idx & 15) * 4;
        int gr = qt * 128 + row;
        cp_async16(&Qs[row * 68 + c4], qb + (long long)gr * 2304 + c4, gr < Sc ? 16 : 0);
    }
    auto issueK = [&](int kt_, int buf) {
#pragma unroll
        for (int i = 0; i < 4; i++) {
            int idx = t + i * 256;
            int hd = idx >> 4, c4 = (idx & 15) * 4;
            cp_async16(&Ks[(buf * 64 + hd) * 72 + c4], kb + hd * KTW + kt_ * 64 + c4, 16);
        }
    };
    auto issueV = [&](int kt_, int buf) {
#pragma unroll
        for (int i = 0; i < 4; i++) {
            int idx = t + i * 256;
            int row = idx >> 4, c4 = (idx & 15) * 4;
            int gk = kt_ * 64 + row;
            cp_async16(&Vs[(buf * 64 + row) * 72 + c4],
                       qb + (long long)gk * 2304 + 128 + c4, gk < Sc ? 16 : 0);
        }
    };
    issueK(0, 0);
    issueV(0, 0);
    asm volatile("cp.async.commit_group;\n");

    float accO[8][4] = {};
    float mr0 = -1e30f, mr1 = -1e30f, lr0 = 0.f, lr1 = 0.f;
    float* Pw = Ps + w * 16 * 68;
    const int nt = (Sc + 63) / 64;

    for (int kt_ = 0; kt_ < nt; kt_++) {
        int buf = kt_ & 1;
        __syncthreads();
        if (kt_ + 1 < nt) { issueK(kt_ + 1, buf ^ 1); issueV(kt_ + 1, buf ^ 1); }
        asm volatile("cp.async.commit_group;\n");
        asm volatile("cp.async.wait_group 1;\n");
        __syncthreads();

        float s[8][4] = {};
        const float* Kb = Ks + buf * 64 * 72;
#pragma unroll
        for (int ks = 0; ks < 8; ks++) {
            int kk = ks * 8;
            uint32_t af[4];
            af[0] = __float_as_uint(Qs[(w * 16 + g) * 68 + kk + tig]);
            af[1] = __float_as_uint(Qs[(w * 16 + g + 8) * 68 + kk + tig]);
            af[2] = __float_as_uint(Qs[(w * 16 + g) * 68 + kk + tig + 4]);
            af[3] = __float_as_uint(Qs[(w * 16 + g + 8) * 68 + kk + tig + 4]);
#pragma unroll
            for (int nf = 0; nf < 8; nf++) {
                uint32_t bf[2];
                bf[0] = __float_as_uint(Kb[(kk + tig) * 72 + nf * 8 + g]);
                bf[1] = __float_as_uint(Kb[(kk + tig + 4) * 72 + nf * 8 + g]);
                mma_tf32(s[nf], af, bf);
            }
        }
        float rm0 = -1e30f, rm1 = -1e30f;
#pragma unroll
        for (int nf = 0; nf < 8; nf++) {
#pragma unroll
            for (int cc = 0; cc < 4; cc++) {
                int col = kt_ * 64 + nf * 8 + tig * 2 + (cc & 1);
                float v = s[nf][cc] * 0.125f;
                v = (col < Sc) ? v : -1e30f;
                s[nf][cc] = v;
                if (cc < 2) rm0 = fmaxf(rm0, v); else rm1 = fmaxf(rm1, v);
            }
        }
        rm0 = fmaxf(rm0, __shfl_xor_sync(0xffffffffu, rm0, 1));
        rm0 = fmaxf(rm0, __shfl_xor_sync(0xffffffffu, rm0, 2));
        rm1 = fmaxf(rm1, __shfl_xor_sync(0xffffffffu, rm1, 1));
        rm1 = fmaxf(rm1, __shfl_xor_sync(0xffffffffu, rm1, 2));
        float nm0 = fmaxf(mr0, rm0), nm1 = fmaxf(mr1, rm1);
        float cor0 = __expf(mr0 - nm0), cor1 = __expf(mr1 - nm1);
        float rs0 = 0.f, rs1 = 0.f;
#pragma unroll
        for (int nf = 0; nf < 8; nf++) {
            int colb = nf * 8 + tig * 2;
            float p0 = __expf(s[nf][0] - nm0);
            float p1 = __expf(s[nf][1] - nm0);
            float p2 = __expf(s[nf][2] - nm1);
            float p3 = __expf(s[nf][3] - nm1);
            rs0 += p0 + p1; rs1 += p2 + p3;
            Pw[g * 68 + colb]       = f2tf_f(p0);
            Pw[g * 68 + colb + 1]   = f2tf_f(p1);
            Pw[(g + 8) * 68 + colb]     = f2tf_f(p2);
            Pw[(g + 8) * 68 + colb + 1] = f2tf_f(p3);
        }
        rs0 += __shfl_xor_sync(0xffffffffu, rs0, 1);
        rs0 += __shfl_xor_sync(0xffffffffu, rs0, 2);
        rs1 += __shfl_xor_sync(0xffffffffu, rs1, 1);
        rs1 += __shfl_xor_sync(0xffffffffu, rs1, 2);
        lr0 = lr0 * cor0 + rs0;
        lr1 = lr1 * cor1 + rs1;
        mr0 = nm0; mr1 = nm1;
#pragma unroll
        for (int nf = 0; nf < 8; nf++) {
            accO[nf][0] *= cor0; accO[nf][1] *= cor0;
            accO[nf][2] *= cor1; accO[nf][3] *= cor1;
        }
        __syncwarp();
        const float* Vb = Vs + buf * 64 * 72;
#pragma unroll
        for (int ks = 0; ks < 8; ks++) {
            int kk = ks * 8;
            uint32_t af[4];
            af[0] = __float_as_uint(Pw[g * 68 + kk + tig]);
            af[1] = __float_as_uint(Pw[(g + 8) * 68 + kk + tig]);
            af[2] = __float_as_uint(Pw[g * 68 + kk + tig + 4]);
            af[3] = __float_as_uint(Pw[(g + 8) * 68 + kk + tig + 4]);
#pragma unroll
            for (int nf = 0; nf < 8; nf++) {
                uint32_t bf[2];
                bf[0] = __float_as_uint(Vb[(kk + tig) * 72 + nf * 8 + g]);
                bf[1] = __float_as_uint(Vb[(kk + tig + 4) * 72 + nf * 8 + g]);
                mma_tf32(accO[nf], af, bf);
            }
        }
    }

    float inv0 = 1.0f / lr0, inv1 = 1.0f / lr1;
    int r0 = qt * 128 + w * 16 + g;
    int r1 = r0 + 8;
#pragma unroll
    for (int nf = 0; nf < 8; nf++) {
        int colb = nf * 8 + tig * 2;
        if (r0 < Sc) {
            om2[((long long)b * Sc + r0) * Dc + h * 64 + colb]     = __float2half(accO[nf][0] * inv0);
            om2[((long long)b * Sc + r0) * Dc + h * 64 + colb + 1] = __float2half(accO[nf][1] * inv0);
        }
        if (r1 < Sc) {
            om2[((long long)b * Sc + r1) * Dc + h * 64 + colb]     = __float2half(accO[nf][2] * inv1);
            om2[((long long)b * Sc + r1) * Dc + h * 64 + colb + 1] = __float2half(accO[nf][3] * inv1);
        }
    }
}

// ---------------- K transpose ----------------
__global__ void ktrans_kernel(const float* __restrict__ qkv, float* __restrict__ kT) {
    __shared__ float tile[32][33];
    int ktile = blockIdx.x;
    int hdt = blockIdx.y;
    int bh = blockIdx.z;
    int b = bh / Hc, h = bh % Hc;
    int tx = threadIdx.x, ty = threadIdx.y;
#pragma unroll
    for (int j = 0; j < 4; j++) {
        int key = ktile * 32 + ty + j * 8;
        int hd = hdt * 32 + tx;
        float v = 0.f;
        if (key < Sc) v = qkv[((long long)b * Sc + key) * 2304 + h * 192 + 64 + hd];
        tile[ty + j * 8][tx] = v;
    }
    __syncthreads();
#pragma unroll
    for (int j = 0; j < 4; j++) {
        int hd = hdt * 32 + ty + j * 8;
        int key = ktile * 32 + tx;
        kT[((long long)bh * HDc + hd) * KTW + key] = tile[tx][ty + j * 8];
    }
}

// ---------------- producers / prep ----------------
__global__ void im2col_kernel(const float* __restrict__ x, __half* __restrict__ col) {
    long long idx = (long long)blockIdx.x * blockDim.x + threadIdx.x;
    long long total = (long long)Bc * NP * Dc;
    if (idx >= total) return;
    int k = (int)(idx % Dc);
    int rem = (int)(idx / Dc);
    int p = rem % NP;
    int b = rem / NP;
    int ph = p / GRID24, pw = p % GRID24;
    int ci = k / 256, k2 = k % 256;
    int kh = k2 / 16, kw = k2 % 16;
    col[idx] = __float2half(x[(((long long)b * 3 + ci) * IMGc + ph * 16 + kh) * IMGc + pw * 16 + kw]);
}

__global__ void transpose_wqkv_kernel(const float* __restrict__ w, __half* __restrict__ wt) {
    long long idx = (long long)blockIdx.x * blockDim.x + threadIdx.x;
    long long total = (long long)Lc * 3 * Dc * Dc;
    if (idx >= total) return;
    int d = (int)(idx % Dc);
    int rem = (int)(idx / Dc);
    int n = rem % (3 * Dc);
    int l = rem / (3 * Dc);
    int h = n / 192, e = n % 192;
    wt[idx] = __float2half(w[(((long long)l * Hc + h) * Dc + d) * 192 + e]);
}

// batched transpose to fp16: out[l][c][r] = half(in[l][r][c])
__global__ void btrans_h_kernel(const float* __restrict__ in, __half* __restrict__ out,
                                int R, int Cn) {
    __shared__ float tile[32][33];
    int ct = blockIdx.x, rt = blockIdx.y, l = blockIdx.z;
    const float* inl = in + (long long)l * R * Cn;
    __half* outl = out + (long long)l * R * Cn;
    int tx = threadIdx.x, ty = threadIdx.y;
#pragma unroll
    for (int j = 0; j < 4; j++) {
        int r = rt * 32 + ty + j * 8;
        int c = ct * 32 + tx;
        tile[ty + j * 8][tx] = (r < R && c < Cn) ? inl[(long long)r * Cn + c] : 0.f;
    }
    __syncthreads();
#pragma unroll
    for (int j = 0; j < 4; j++) {
        int c = ct * 32 + ty + j * 8;
        int r = rt * 32 + tx;
        if (c < Cn && r < R)
            outl[(long long)c * R + r] = __float2half(tile[tx][ty + j * 8]);
    }
}

__global__ void hcopy_kernel(const float* __restrict__ w, __half* __restrict__ o, long long n) {
    long long i = (long long)blockIdx.x * blockDim.x + threadIdx.x;
    if (i < n) o[i] = __float2half(w[i]);
}

__global__ void embed_kernel(const float* __restrict__ pout, const float* __restrict__ cls,
                             const float* __restrict__ pos, float* __restrict__ t) {
    long long idx = (long long)blockIdx.x * blockDim.x + threadIdx.x;
    long long total = (long long)Bc * Sc * Dc;
    if (idx >= total) return;
    int j = (int)(idx % Dc);
    int rem = (int)(idx / Dc);
    int r = rem % Sc;
    int b = rem / Sc;
    float v;
    if (r == 0) {
        v = cls[j];
    } else {
        int i = (r - 1) * Dc + j;
        int c = i / NP, p = i % NP;
        v = pout[((long long)b * NP + p) * Dc + c];
    }
    t[idx] = v + pos[r * Dc + j];
}

// LN writing fp32 (optional) + fp16 (optional)
__global__ void layernorm_kernel(const float* __restrict__ x, const float* __restrict__ g,
                                 const float* __restrict__ b, float* __restrict__ yf,
                                 __half* __restrict__ y2, int rows, int rnd) {
    __shared__ float red[256];
    int row = blockIdx.x;
    if (row >= rows) return;
    int t = threadIdx.x;
    const float* xr = x + (long long)row * Dc;
    float v[3];
    float s = 0.f;
#pragma unroll
    for (int i = 0; i < 3; i++) { v[i] = xr[t + i * 256]; s += v[i]; }
    red[t] = s; __syncthreads();
    for (int o = 128; o > 0; o >>= 1) { if (t < o) red[t] += red[t + o]; __syncthreads(); }
    float mu = red[0] / Dc;
    __syncthreads();
    float s2 = 0.f;
#pragma unroll
    for (int i = 0; i < 3; i++) { float d = v[i] - mu; s2 += d * d; }
    red[t] = s2; __syncthreads();
    for (int o = 128; o > 0; o >>= 1) { if (t < o) red[t] += red[t + o]; __syncthreads(); }
    float rstd = rsqrtf(red[0] / Dc + 1e-5f);
#pragma unroll
    for (int i = 0; i < 3; i++) {
        int j = t + i * 256;
        float val = (v[i] - mu) * rstd * g[j] + b[j];
        if (yf) yf[(long long)row * Dc + j] = rnd ? f2tf_f(val) : val;
        if (y2) y2[(long long)row * Dc + j] = __float2half(val);
    }
}

// fused double layernorm -> fp16 only
__global__ void layernorm2_kernel(const float* __restrict__ x,
                                  const float* __restrict__ g1, const float* __restrict__ b1,
                                  const float* __restrict__ g2, const float* __restrict__ b2,
                                  __half* __restrict__ y2, int rows) {
    __shared__ float red[256];
    int row = blockIdx.x;
    if (row >= rows) return;
    int t = threadIdx.x;
    const float* xr = x + (long long)row * Dc;
    float v[3];
    float s = 0.f;
#pragma unroll
    for (int i = 0; i < 3; i++) { v[i] = xr[t + i * 256]; s += v[i]; }
    red[t] = s; __syncthreads();
    for (int o = 128; o > 0; o >>= 1) { if (t < o) red[t] += red[t + o]; __syncthreads(); }
    float mu = red[0] / Dc;
    __syncthreads();
    float s2 = 0.f;
#pragma unroll
    for (int i = 0; i < 3; i++) { float d = v[i] - mu; s2 += d * d; }
    red[t] = s2; __syncthreads();
    for (int o = 128; o > 0; o >>= 1) { if (t < o) red[t] += red[t + o]; __syncthreads(); }
    float rstd = rsqrtf(red[0] / Dc + 1e-5f);
    __syncthreads();
    s = 0.f;
#pragma unroll
    for (int i = 0; i < 3; i++) {
        int j = t + i * 256;
        v[i] = (v[i] - mu) * rstd * g1[j] + b1[j];
        s += v[i];
    }
    red[t] = s; __syncthreads();
    for (int o = 128; o > 0; o >>= 1) { if (t < o) red[t] += red[t + o]; __syncthreads(); }
    mu = red[0] / Dc;
    __syncthreads();
    s2 = 0.f;
#pragma unroll
    for (int i = 0; i < 3; i++) { float d = v[i] - mu; s2 += d * d; }
    red[t] = s2; __syncthreads();
    for (int o = 128; o > 0; o >>= 1) { if (t < o) red[t] += red[t + o]; __syncthreads(); }
    rstd = rsqrtf(red[0] / Dc + 1e-5f);
#pragma unroll
    for (int i = 0; i < 3; i++) {
        int j = t + i * 256;
        y2[(long long)row * Dc + j] = __float2half((v[i] - mu) * rstd * g2[j] + b2[j]);
    }
}

__global__ void softmax_kernel(float* __restrict__ x, long long rows, int n) {
    __shared__ float red[256];
    long long row = blockIdx.x;
    if (row >= rows) return;
    int t = threadIdx.x;
    float* xr = x + row * n;
    float lmax = -1e30f;
    for (int j = t; j < n; j += 256) lmax = fmaxf(lmax, xr[j]);
    red[t] = lmax; __syncthreads();
    for (int o = 128; o > 0; o >>= 1) { if (t < o) red[t] = fmaxf(red[t], red[t + o]); __syncthreads(); }
    float mx = red[0];
    __syncthreads();
    float ls = 0.f;
    for (int j = t; j < n; j += 256) { float e = expf(xr[j] - mx); xr[j] = e; ls += e; }
    red[t] = ls; __syncthreads();
    for (int o = 128; o > 0; o >>= 1) { if (t < o) red[t] += red[t + o]; __syncthreads(); }
    float inv = 1.0f / red[0];
    for (int j = t; j < n; j += 256) xr[j] *= inv;
}

__global__ void extract_cls_kernel(const float* __restrict__ t, float* __restrict__ cls) {
    int idx = blockIdx.x * blockDim.x + threadIdx.x;
    if (idx >= Bc * Dc) return;
    int b = idx / Dc, j = idx % Dc;
    cls[idx] = t[((long long)b * Sc) * Dc + j];
}

// ---------------- host helpers ----------------
static void run_hgemm(const __half* A, const __half* Bm, const float* bias,
                      const float* res, float* Cf, __half* C2, int M, int N, int K,
                      int ldc, int act, int rnd) {
    dim3 grid((N + 127) / 128, (M + 127) / 128, 1);
    hgemm_kernel<<<grid, 256, GEMM_SMEM>>>(A, Bm, bias, res, Cf, C2, M, N, K, ldc, act, rnd);
}

extern "C" void kernel_launch(void* const* d_in, const int* in_sizes, int n_in,
                              void* d_out, int out_size) {
    const float* x       = (const float*)d_in[0];
    const float* conv_w  = (const float*)d_in[1];
    const float* conv_b  = (const float*)d_in[2];
    const float* cls_tok = (const float*)d_in[3];
    const float* pos_emb = (const float*)d_in[4];
    const float* ln1_g   = (const float*)d_in[5];
    const float* ln1_b   = (const float*)d_in[6];
    const float* wqkv    = (const float*)d_in[7];
    const float* bqkv    = (const float*)d_in[8];
    const float* wmsa    = (const float*)d_in[9];
    const float* bmsa    = (const float*)d_in[10];
    const float* ln2_g   = (const float*)d_in[11];
    const float* ln2_b   = (const float*)d_in[12];
    const float* lnm_g   = (const float*)d_in[13];
    const float* lnm_b   = (const float*)d_in[14];
    const float* w1      = (const float*)d_in[15];
    const float* b1      = (const float*)d_in[16];
    const float* w2      = (const float*)d_in[17];
    const float* b2      = (const float*)d_in[18];
    const float* lnf_g   = (const float*)d_in[19];
    const float* lnf_b   = (const float*)d_in[20];
    const float* whead   = (const float*)d_in[21];
    const float* bhead   = (const float*)d_in[22];
    float* out = (float*)d_out;

    float *t_, *h_, *qkv_, *kT_, *cls_;
    __half *h2_, *om2_, *mb2_, *col2_, *cls2_, *wq2_, *cw2_, *wm2_, *w12_, *w22_, *wh2_;
    cudaGetSymbolAddress((void**)&t_,  g_t);
    cudaGetSymbolAddress((void**)&h_,  g_h);
    cudaGetSymbolAddress((void**)&qkv_, g_qkv);
    cudaGetSymbolAddress((void**)&kT_, g_kT);
    cudaGetSymbolAddress((void**)&cls_, g_cls);
    cudaGetSymbolAddress((void**)&h2_, g_h2);
    cudaGetSymbolAddress((void**)&om2_, g_om2);
    cudaGetSymbolAddress((void**)&mb2_, g_mb2);
    cudaGetSymbolAddress((void**)&col2_, g_col2);
    cudaGetSymbolAddress((void**)&cls2_, g_cls2);
    cudaGetSymbolAddress((void**)&wq2_, g_wq2);
    cudaGetSymbolAddress((void**)&cw2_, g_cw2);
    cudaGetSymbolAddress((void**)&wm2_, g_wm2);
    cudaGetSymbolAddress((void**)&w12_, g_w12);
    cudaGetSymbolAddress((void**)&w22_, g_w22);
    cudaGetSymbolAddress((void**)&wh2_, g_wh2);

    cudaFuncSetAttribute(flash_kernel, cudaFuncAttributeMaxDynamicSharedMemorySize, 143360);
    cudaFuncSetAttribute(hgemm_kernel, cudaFuncAttributeMaxDynamicSharedMemorySize, GEMM_SMEM);

    // --- weight prep: fp16, transposed to [N][K] ---
    hcopy_kernel<<<(Dc * Dc + 255) / 256, 256>>>(conv_w, cw2_, (long long)Dc * Dc);
    {
        long long tot = (long long)Lc * 3 * Dc * Dc;
        transpose_wqkv_kernel<<<(int)((tot + 255) / 256), 256>>>(wqkv, wq2_);
    }
    {
        dim3 tb(32, 8);
        btrans_h_kernel<<<dim3(Dc / 32, Dc / 32, Lc), tb>>>(wmsa, wm2_, Dc, Dc);
        btrans_h_kernel<<<dim3(Mc / 32, Dc / 32, Lc), tb>>>(w1, w12_, Dc, Mc);
        btrans_h_kernel<<<dim3(Dc / 32, Mc / 32, Lc), tb>>>(w2, w22_, Mc, Dc);
        btrans_h_kernel<<<dim3((NCc + 31) / 32, Dc / 32, 1), tb>>>(whead, wh2_, Dc, NCc);
    }

    // --- patchify ---
    {
        long long tot = (long long)Bc * NP * Dc;
        im2col_kernel<<<(int)((tot + 255) / 256), 256>>>(x, col2_);
    }
    run_hgemm(col2_, cw2_, conv_b, nullptr, h_, nullptr, Bc * NP, Dc, Dc, Dc, 0, 0);
    {
        long long tot = (long long)Bc * Sc * Dc;
        embed_kernel<<<(int)((tot + 255) / 256), 256>>>(h_, cls_tok, pos_emb, t_);
    }

    // --- encoder layers ---
    for (int l = 0; l < Lc; l++) {
        // ln1 -> h_ (fp32, residual) + h2 (fp16, gemm A)
        layernorm_kernel<<<BS, 256>>>(t_, ln1_g + l * Dc, ln1_b + l * Dc, h_, h2_, BS, 0);
        // qkv = h2 @ wq2 + bqkv  (fp32 out, tf32-rounded for flash)
        run_hgemm(h2_, wq2_ + (long long)l * 3 * Dc * Dc, bqkv + l * 3 * Dc, nullptr,
                  qkv_, nullptr, BS, 3 * Dc, Dc, 3 * Dc, 0, 1);
        ktrans_kernel<<<dim3(KTW / 32, 2, Bc * Hc), dim3(32, 8)>>>(qkv_, kT_);
        flash_kernel<<<dim3((Sc + 127) / 128, Hc, Bc), 256, 143360>>>(qkv_, kT_, om2_);
        // msa: t = om2 @ wm2 + bmsa + h_
        run_hgemm(om2_, wm2_ + (long long)l * Dc * Dc, bmsa + l * Dc, h_,
                  t_, nullptr, BS, Dc, Dc, Dc, 0, 0);
        // double LN -> h2
        layernorm2_kernel<<<BS, 256>>>(t_, ln2_g + l * Dc, ln2_b + l * Dc,
                                       lnm_g + l * Dc, lnm_b + l * Dc, h2_, BS);
        // mlp1: mb2 = gelu(h2 @ w12 + b1)  (fp16 out)
        run_hgemm(h2_, w12_ + (long long)l * Mc * Dc, b1 + l * Mc, nullptr,
                  nullptr, mb2_, BS, Mc, Dc, Mc, 1, 0);
        // mlp2: t = mb2 @ w22 + b2 + t
        run_hgemm(mb2_, w22_ + (long long)l * Dc * Mc, b2 + l * Dc, t_,
                  t_, nullptr, BS, Dc, Mc, Dc, 0, 0);
    }

    // --- head ---
    extract_cls_kernel<<<(Bc * Dc + 255) / 256, 256>>>(t_, cls_);
    layernorm_kernel<<<Bc, 256>>>(cls_, lnf_g, lnf_b, nullptr, cls2_, Bc, 0);
    run_hgemm(cls2_, wh2_, bhead, nullptr, out, nullptr, Bc, NCc, Dc, NCc, 0, 0);
    softmax_kernel<<<Bc, 256>>>(out, Bc, NCc);
}

// round 10
// speedup vs baseline: 1.7820x; 1.1340x over previous
#include <cuda_runtime.h>
#include <cuda_fp16.h>
#include <math.h>
#include <stdint.h>

// ---------------- dims ----------------
static const int Lc = 12, Hc = 12, Dc = 768, HDc = 64, Mc = 3072;
static const int IMGc = 384, Bc = 32, NCc = 1000;
static const int NP = 576;
static const int Sc = 577;
static const int BS = Bc * Sc;        // 18464
static const int GRID24 = 24;
static const int GS = 4;              // gemm pipeline stages

// ---------------- scratch ----------------
__device__ float g_t[BS * Dc];                 // residual (fp32)
__device__ float g_h[BS * Dc];                 // ln1 out fp32 (msa residual)
__device__ float g_cls[Bc * Dc];
// fp16 operands
__device__ __half g_h2[BS * Dc];
__device__ __half g_om2[BS * Dc];
__device__ __half g_mb2[(long long)BS * Mc];
__device__ __half g_qkv2[(long long)BS * 3 * Dc];
__device__ __half g_col2[Bc * NP * Dc];
__device__ __half g_cls2[Bc * Dc];
__device__ __half g_wq2[(long long)Lc * 3 * Dc * Dc];  // [l][n=2304][k=768]
__device__ __half g_cw2[Dc * Dc];                      // [n][k]
__device__ __half g_wm2[(long long)Lc * Dc * Dc];
__device__ __half g_w12[(long long)Lc * Mc * Dc];
__device__ __half g_w22[(long long)Lc * Dc * Mc];
__device__ __half g_wh2[NCc * Dc];

// ---------------- helpers ----------------
__device__ __forceinline__ void mma_f16(float c[4], const uint32_t a[4], const uint32_t b[2]) {
    asm volatile(
        "mma.sync.aligned.m16n8k16.row.col.f32.f16.f16.f32 "
        "{%0,%1,%2,%3}, {%4,%5,%6,%7}, {%8,%9}, {%0,%1,%2,%3};\n"
        : "+f"(c[0]), "+f"(c[1]), "+f"(c[2]), "+f"(c[3])
        : "r"(a[0]), "r"(a[1]), "r"(a[2]), "r"(a[3]), "r"(b[0]), "r"(b[1]));
}

__device__ __forceinline__ void cp_async16(void* smem_dst, const void* gsrc, int sz) {
    unsigned sm = (unsigned)__cvta_generic_to_shared(smem_dst);
    asm volatile("cp.async.ca.shared.global [%0], [%1], 16, %2;\n" :: "r"(sm), "l"(gsrc), "r"(sz));
}

__device__ __forceinline__ void ldsm4h(uint32_t r[4], const __half* p) {
    unsigned a = (unsigned)__cvta_generic_to_shared(p);
    asm volatile("ldmatrix.sync.aligned.m8n8.x4.shared.b16 {%0,%1,%2,%3}, [%4];\n"
                 : "=r"(r[0]), "=r"(r[1]), "=r"(r[2]), "=r"(r[3]) : "r"(a));
}
__device__ __forceinline__ void ldsm4h_trans(uint32_t r[4], const __half* p) {
    unsigned a = (unsigned)__cvta_generic_to_shared(p);
    asm volatile("ldmatrix.sync.aligned.m8n8.x4.trans.shared.b16 {%0,%1,%2,%3}, [%4];\n"
                 : "=r"(r[0]), "=r"(r[1]), "=r"(r[2]), "=r"(r[3]) : "r"(a));
}

// ---------------- fp16 tensor GEMM (verified R9) ----------------
static const int HROW = 40;
static const int HSTG = 128 * HROW;
static const int GEMM_SMEM = GS * 2 * HSTG * 2;  // 81920 bytes

__global__ void __launch_bounds__(256, 2)
hgemm_kernel(const __half* __restrict__ A, const __half* __restrict__ Bm,
             const float* __restrict__ bias, const float* __restrict__ res,
             float* __restrict__ Cf, __half* __restrict__ C2,
             int M, int N, int K, int ldc, int act) {
    extern __shared__ __half smh[];

    int t = threadIdx.x;
    int lane = t & 31, wid = t >> 5;
    int wm = wid >> 2, wn = wid & 3;
    int g = lane >> 2, tig = lane & 3;
    int m0 = blockIdx.y * 128, n0 = blockIdx.x * 128;

    float acc[4][4][4] = {};
    int nk = K / 32;

    auto loadTile = [&](int k0, int s) {
        __half* dstA = smh + s * 2 * HSTG;
        __half* dstB = dstA + HSTG;
#pragma unroll
        for (int i = 0; i < 2; i++) {
            int c = t + i * 256;
            int r = c >> 2, sg = (c & 3) * 8;
            cp_async16(dstA + r * HROW + sg, A + (long long)(m0 + r) * K + k0 + sg,
                       (m0 + r < M) ? 16 : 0);
        }
#pragma unroll
        for (int i = 0; i < 2; i++) {
            int c = t + i * 256;
            int r = c >> 2, sg = (c & 3) * 8;
            cp_async16(dstB + r * HROW + sg, Bm + (long long)(n0 + r) * K + k0 + sg,
                       (n0 + r < N) ? 16 : 0);
        }
    };

#pragma unroll
    for (int s = 0; s < GS - 1; s++) {
        loadTile(s * 32, s);
        asm volatile("cp.async.commit_group;\n");
    }

    int a_row = wm * 64 + (lane & 15);
    int a_cofs = (lane >> 4) << 3;
    int b_row = wn * 32 + ((lane >> 4) << 3) + (lane & 7);
    int b_cofs = ((lane >> 3) & 1) << 3;

    for (int it = 0; it < nk; it++) {
        asm volatile("cp.async.wait_group %0;\n" :: "n"(GS - 2));
        __syncthreads();
        if (it + GS - 1 < nk) loadTile((it + GS - 1) * 32, (it + GS - 1) % GS);
        asm volatile("cp.async.commit_group;\n");

        const __half* Ab = smh + (it % GS) * 2 * HSTG;
        const __half* Bb = Ab + HSTG;
#pragma unroll
        for (int ks = 0; ks < 2; ks++) {
            int kc = ks * 16;
            uint32_t af[4][4], bq[2][4];
#pragma unroll
            for (int mt = 0; mt < 4; mt++)
                ldsm4h(af[mt], Ab + (a_row + mt * 16) * HROW + kc + a_cofs);
#pragma unroll
            for (int nb = 0; nb < 2; nb++)
                ldsm4h(bq[nb], Bb + (b_row + nb * 16) * HROW + kc + b_cofs);
#pragma unroll
            for (int mt = 0; mt < 4; mt++)
#pragma unroll
                for (int nt = 0; nt < 4; nt++) {
                    uint32_t b2[2] = { bq[nt >> 1][(nt & 1) * 2], bq[nt >> 1][(nt & 1) * 2 + 1] };
                    mma_f16(acc[mt][nt], af[mt], b2);
                }
        }
    }

#pragma unroll
    for (int mt = 0; mt < 4; mt++) {
#pragma unroll
        for (int nt = 0; nt < 4; nt++) {
            int row = m0 + wm * 64 + mt * 16 + g;
            int col = n0 + wn * 32 + nt * 8 + tig * 2;
#pragma unroll
            for (int cc = 0; cc < 4; cc++) {
                int m = row + (cc >> 1) * 8;
                int n = col + (cc & 1);
                if (m >= M || n >= N) continue;
                float v = acc[mt][nt][cc];
                if (bias) v += bias[n];
                if (res) v += res[(long long)m * ldc + n];
                if (act == 1) v = 0.5f * v * (1.0f + erff(v * 0.7071067811865476f));
                if (Cf) Cf[(long long)m * ldc + n] = v;
                if (C2) C2[(long long)m * ldc + n] = __float2half(v);
            }
        }
    }
}

// ---------------- fp16 flash attention ----------------
// smem halves: Qs[128][72] | Ps[8][16][72] | Ks[2][64][72] | Vs[2][64][72]
static const int FLASH_SMEM = (9216 + 9216 + 9216 + 9216) * 2;   // 73728 B

__global__ void __launch_bounds__(256)
flash_kernel(const __half* __restrict__ qkv, __half* __restrict__ om2) {
    extern __shared__ __half smh[];
    __half* Qs = smh;               // [128][72]
    __half* Ps = smh + 9216;        // [8][16][72]
    __half* Ks = smh + 18432;       // [2][64][72]
    __half* Vs = smh + 27648;       // [2][64][72]

    int qt = blockIdx.x, h = blockIdx.y, b = blockIdx.z;
    int t = threadIdx.x, lane = t & 31, w = t >> 5, g = lane >> 2, tig = lane & 3;
    const __half* qb = qkv + (long long)b * Sc * 2304 + h * 192;

    // Q tile 128x64 halves
#pragma unroll
    for (int i = 0; i < 4; i++) {
        int idx = t + i * 256;
        int row = idx >> 3, sg = idx & 7;
        int gr = qt * 128 + row;
        cp_async16(Qs + row * 72 + sg * 8, qb + (long long)gr * 2304 + sg * 8, gr < Sc ? 16 : 0);
    }
    auto issueK = [&](int kt_, int buf) {
#pragma unroll
        for (int i = 0; i < 2; i++) {
            int idx = t + i * 256;
            int row = idx >> 3, sg = idx & 7;
            int gk = kt_ * 64 + row;
            cp_async16(Ks + (buf * 64 + row) * 72 + sg * 8,
                       qb + (long long)gk * 2304 + 64 + sg * 8, gk < Sc ? 16 : 0);
        }
    };
    auto issueV = [&](int kt_, int buf) {
#pragma unroll
        for (int i = 0; i < 2; i++) {
            int idx = t + i * 256;
            int row = idx >> 3, sg = idx & 7;
            int gk = kt_ * 64 + row;
            cp_async16(Vs + (buf * 64 + row) * 72 + sg * 8,
                       qb + (long long)gk * 2304 + 128 + sg * 8, gk < Sc ? 16 : 0);
        }
    };
    issueK(0, 0);
    issueV(0, 0);
    asm volatile("cp.async.commit_group;\n");

    float accO[8][4] = {};
    float mr0 = -1e30f, mr1 = -1e30f, lr0 = 0.f, lr1 = 0.f;
    __half* Pw = Ps + w * 16 * 72;
    const __half* Qw = Qs + w * 16 * 72;
    const int nt = (Sc + 63) / 64;   // 10

    int arow = lane & 15;
    int acof = (lane >> 4) << 3;
    int brow = ((lane >> 4) << 3) + (lane & 7);
    int bcof = ((lane >> 3) & 1) << 3;

    for (int kt_ = 0; kt_ < nt; kt_++) {
        int buf = kt_ & 1;
        __syncthreads();
        if (kt_ + 1 < nt) { issueK(kt_ + 1, buf ^ 1); issueV(kt_ + 1, buf ^ 1); }
        asm volatile("cp.async.commit_group;\n");
        asm volatile("cp.async.wait_group 1;\n");
        __syncthreads();

        // S = Q @ K^T : A=Q[16][64], B=K[key][hd] (=[n][k])
        float s[8][4] = {};
        const __half* Kb = Ks + buf * 64 * 72;
#pragma unroll
        for (int ks = 0; ks < 4; ks++) {
            int kc = ks * 16;
            uint32_t af[4];
            ldsm4h(af, Qw + arow * 72 + kc + acof);
#pragma unroll
            for (int nb = 0; nb < 4; nb++) {
                uint32_t bq[4];
                ldsm4h(bq, Kb + (nb * 16 + brow) * 72 + kc + bcof);
#pragma unroll
                for (int blk = 0; blk < 2; blk++) {
                    uint32_t b2[2] = { bq[blk * 2], bq[blk * 2 + 1] };
                    mma_f16(s[nb * 2 + blk], af, b2);
                }
            }
        }
        // scale + mask + online softmax
        float rm0 = -1e30f, rm1 = -1e30f;
#pragma unroll
        for (int nf = 0; nf < 8; nf++) {
#pragma unroll
            for (int cc = 0; cc < 4; cc++) {
                int col = kt_ * 64 + nf * 8 + tig * 2 + (cc & 1);
                float v = s[nf][cc] * 0.125f;
                v = (col < Sc) ? v : -1e30f;
                s[nf][cc] = v;
                if (cc < 2) rm0 = fmaxf(rm0, v); else rm1 = fmaxf(rm1, v);
            }
        }
        rm0 = fmaxf(rm0, __shfl_xor_sync(0xffffffffu, rm0, 1));
        rm0 = fmaxf(rm0, __shfl_xor_sync(0xffffffffu, rm0, 2));
        rm1 = fmaxf(rm1, __shfl_xor_sync(0xffffffffu, rm1, 1));
        rm1 = fmaxf(rm1, __shfl_xor_sync(0xffffffffu, rm1, 2));
        float nm0 = fmaxf(mr0, rm0), nm1 = fmaxf(mr1, rm1);
        float cor0 = __expf(mr0 - nm0), cor1 = __expf(mr1 - nm1);
        float rs0 = 0.f, rs1 = 0.f;
#pragma unroll
        for (int nf = 0; nf < 8; nf++) {
            int colb = nf * 8 + tig * 2;
            float p0 = __expf(s[nf][0] - nm0);
            float p1 = __expf(s[nf][1] - nm0);
            float p2 = __expf(s[nf][2] - nm1);
            float p3 = __expf(s[nf][3] - nm1);
            rs0 += p0 + p1; rs1 += p2 + p3;
            Pw[g * 72 + colb]           = __float2half(p0);
            Pw[g * 72 + colb + 1]       = __float2half(p1);
            Pw[(g + 8) * 72 + colb]     = __float2half(p2);
            Pw[(g + 8) * 72 + colb + 1] = __float2half(p3);
        }
        rs0 += __shfl_xor_sync(0xffffffffu, rs0, 1);
        rs0 += __shfl_xor_sync(0xffffffffu, rs0, 2);
        rs1 += __shfl_xor_sync(0xffffffffu, rs1, 1);
        rs1 += __shfl_xor_sync(0xffffffffu, rs1, 2);
        lr0 = lr0 * cor0 + rs0;
        lr1 = lr1 * cor1 + rs1;
        mr0 = nm0; mr1 = nm1;
#pragma unroll
        for (int nf = 0; nf < 8; nf++) {
            accO[nf][0] *= cor0; accO[nf][1] *= cor0;
            accO[nf][2] *= cor1; accO[nf][3] *= cor1;
        }
        __syncwarp();
        // O += P @ V : A=P[16][64 keys], B=V^T via ldmatrix.trans on V[key][hd]
        const __half* Vb = Vs + buf * 64 * 72;
#pragma unroll
        for (int ks = 0; ks < 4; ks++) {
            int kc = ks * 16;          // key offset
            uint32_t af[4];
            ldsm4h(af, Pw + arow * 72 + kc + acof);
#pragma unroll
            for (int nb = 0; nb < 4; nb++) {   // hd blocks of 16
                uint32_t vq[4];
                ldsm4h_trans(vq, Vb + (kc + brow) * 72 + nb * 16 + bcof);
#pragma unroll
                for (int blk = 0; blk < 2; blk++) {
                    uint32_t b2[2] = { vq[blk], vq[blk + 2] };
                    mma_f16(accO[nb * 2 + blk], af, b2);
                }
            }
        }
        __syncwarp();
    }

    float inv0 = 1.0f / lr0, inv1 = 1.0f / lr1;
    int r0 = qt * 128 + w * 16 + g;
    int r1 = r0 + 8;
#pragma unroll
    for (int nf = 0; nf < 8; nf++) {
        int colb = nf * 8 + tig * 2;
        if (r0 < Sc) {
            om2[((long long)b * Sc + r0) * Dc + h * 64 + colb]     = __float2half(accO[nf][0] * inv0);
            om2[((long long)b * Sc + r0) * Dc + h * 64 + colb + 1] = __float2half(accO[nf][1] * inv0);
        }
        if (r1 < Sc) {
            om2[((long long)b * Sc + r1) * Dc + h * 64 + colb]     = __float2half(accO[nf][2] * inv1);
            om2[((long long)b * Sc + r1) * Dc + h * 64 + colb + 1] = __float2half(accO[nf][3] * inv1);
        }
    }
}

// ---------------- producers / prep ----------------
__global__ void im2col_kernel(const float* __restrict__ x, __half* __restrict__ col) {
    long long idx = (long long)blockIdx.x * blockDim.x + threadIdx.x;
    long long total = (long long)Bc * NP * Dc;
    if (idx >= total) return;
    int k = (int)(idx % Dc);
    int rem = (int)(idx / Dc);
    int p = rem % NP;
    int b = rem / NP;
    int ph = p / GRID24, pw = p % GRID24;
    int ci = k / 256, k2 = k % 256;
    int kh = k2 / 16, kw = k2 % 16;
    col[idx] = __float2half(x[(((long long)b * 3 + ci) * IMGc + ph * 16 + kh) * IMGc + pw * 16 + kw]);
}

__global__ void transpose_wqkv_kernel(const float* __restrict__ w, __half* __restrict__ wt) {
    long long idx = (long long)blockIdx.x * blockDim.x + threadIdx.x;
    long long total = (long long)Lc * 3 * Dc * Dc;
    if (idx >= total) return;
    int d = (int)(idx % Dc);
    int rem = (int)(idx / Dc);
    int n = rem % (3 * Dc);
    int l = rem / (3 * Dc);
    int h = n / 192, e = n % 192;
    wt[idx] = __float2half(w[(((long long)l * Hc + h) * Dc + d) * 192 + e]);
}

__global__ void btrans_h_kernel(const float* __restrict__ in, __half* __restrict__ out,
                                int R, int Cn) {
    __shared__ float tile[32][33];
    int ct = blockIdx.x, rt = blockIdx.y, l = blockIdx.z;
    const float* inl = in + (long long)l * R * Cn;
    __half* outl = out + (long long)l * R * Cn;
    int tx = threadIdx.x, ty = threadIdx.y;
#pragma unroll
    for (int j = 0; j < 4; j++) {
        int r = rt * 32 + ty + j * 8;
        int c = ct * 32 + tx;
        tile[ty + j * 8][tx] = (r < R && c < Cn) ? inl[(long long)r * Cn + c] : 0.f;
    }
    __syncthreads();
#pragma unroll
    for (int j = 0; j < 4; j++) {
        int c = ct * 32 + ty + j * 8;
        int r = rt * 32 + tx;
        if (c < Cn && r < R)
            outl[(long long)c * R + r] = __float2half(tile[tx][ty + j * 8]);
    }
}

__global__ void hcopy_kernel(const float* __restrict__ w, __half* __restrict__ o, long long n) {
    long long i = (long long)blockIdx.x * blockDim.x + threadIdx.x;
    if (i < n) o[i] = __float2half(w[i]);
}

__global__ void embed_kernel(const float* __restrict__ pout, const float* __restrict__ cls,
                             const float* __restrict__ pos, float* __restrict__ t) {
    long long idx = (long long)blockIdx.x * blockDim.x + threadIdx.x;
    long long total = (long long)Bc * Sc * Dc;
    if (idx >= total) return;
    int j = (int)(idx % Dc);
    int rem = (int)(idx / Dc);
    int r = rem % Sc;
    int b = rem / Sc;
    float v;
    if (r == 0) {
        v = cls[j];
    } else {
        int i = (r - 1) * Dc + j;
        int c = i / NP, p = i % NP;
        v = pout[((long long)b * NP + p) * Dc + c];
    }
    t[idx] = v + pos[r * Dc + j];
}

__global__ void layernorm_kernel(const float* __restrict__ x, const float* __restrict__ g,
                                 const float* __restrict__ b, float* __restrict__ yf,
                                 __half* __restrict__ y2, int rows) {
    __shared__ float red[256];
    int row = blockIdx.x;
    if (row >= rows) return;
    int t = threadIdx.x;
    const float* xr = x + (long long)row * Dc;
    float v[3];
    float s = 0.f;
#pragma unroll
    for (int i = 0; i < 3; i++) { v[i] = xr[t + i * 256]; s += v[i]; }
    red[t] = s; __syncthreads();
    for (int o = 128; o > 0; o >>= 1) { if (t < o) red[t] += red[t + o]; __syncthreads(); }
    float mu = red[0] / Dc;
    __syncthreads();
    float s2 = 0.f;
#pragma unroll
    for (int i = 0; i < 3; i++) { float d = v[i] - mu; s2 += d * d; }
    red[t] = s2; __syncthreads();
    for (int o = 128; o > 0; o >>= 1) { if (t < o) red[t] += red[t + o]; __syncthreads(); }
    float rstd = rsqrtf(red[0] / Dc + 1e-5f);
#pragma unroll
    for (int i = 0; i < 3; i++) {
        int j = t + i * 256;
        float val = (v[i] - mu) * rstd * g[j] + b[j];
        if (yf) yf[(long long)row * Dc + j] = val;
        if (y2) y2[(long long)row * Dc + j] = __float2half(val);
    }
}

__global__ void layernorm2_kernel(const float* __restrict__ x,
                                  const float* __restrict__ g1, const float* __restrict__ b1,
                                  const float* __restrict__ g2, const float* __restrict__ b2,
                                  __half* __restrict__ y2, int rows) {
    __shared__ float red[256];
    int row = blockIdx.x;
    if (row >= rows) return;
    int t = threadIdx.x;
    const float* xr = x + (long long)row * Dc;
    float v[3];
    float s = 0.f;
#pragma unroll
    for (int i = 0; i < 3; i++) { v[i] = xr[t + i * 256]; s += v[i]; }
    red[t] = s; __syncthreads();
    for (int o = 128; o > 0; o >>= 1) { if (t < o) red[t] += red[t + o]; __syncthreads(); }
    float mu = red[0] / Dc;
    __syncthreads();
    float s2 = 0.f;
#pragma unroll
    for (int i = 0; i < 3; i++) { float d = v[i] - mu; s2 += d * d; }
    red[t] = s2; __syncthreads();
    for (int o = 128; o > 0; o >>= 1) { if (t < o) red[t] += red[t + o]; __syncthreads(); }
    float rstd = rsqrtf(red[0] / Dc + 1e-5f);
    __syncthreads();
    s = 0.f;
#pragma unroll
    for (int i = 0; i < 3; i++) {
        int j = t + i * 256;
        v[i] = (v[i] - mu) * rstd * g1[j] + b1[j];
        s += v[i];
    }
    red[t] = s; __syncthreads();
    for (int o = 128; o > 0; o >>= 1) { if (t < o) red[t] += red[t + o]; __syncthreads(); }
    mu = red[0] / Dc;
    __syncthreads();
    s2 = 0.f;
#pragma unroll
    for (int i = 0; i < 3; i++) { float d = v[i] - mu; s2 += d * d; }
    red[t] = s2; __syncthreads();
    for (int o = 128; o > 0; o >>= 1) { if (t < o) red[t] += red[t + o]; __syncthreads(); }
    rstd = rsqrtf(red[0] / Dc + 1e-5f);
#pragma unroll
    for (int i = 0; i < 3; i++) {
        int j = t + i * 256;
        y2[(long long)row * Dc + j] = __float2half((v[i] - mu) * rstd * g2[j] + b2[j]);
    }
}

__global__ void softmax_kernel(float* __restrict__ x, long long rows, int n) {
    __shared__ float red[256];
    long long row = blockIdx.x;
    if (row >= rows) return;
    int t = threadIdx.x;
    float* xr = x + row * n;
    float lmax = -1e30f;
    for (int j = t; j < n; j += 256) lmax = fmaxf(lmax, xr[j]);
    red[t] = lmax; __syncthreads();
    for (int o = 128; o > 0; o >>= 1) { if (t < o) red[t] = fmaxf(red[t], red[t + o]); __syncthreads(); }
    float mx = red[0];
    __syncthreads();
    float ls = 0.f;
    for (int j = t; j < n; j += 256) { float e = expf(xr[j] - mx); xr[j] = e; ls += e; }
    red[t] = ls; __syncthreads();
    for (int o = 128; o > 0; o >>= 1) { if (t < o) red[t] += red[t + o]; __syncthreads(); }
    float inv = 1.0f / red[0];
    for (int j = t; j < n; j += 256) xr[j] *= inv;
}

__global__ void extract_cls_kernel(const float* __restrict__ t, float* __restrict__ cls) {
    int idx = blockIdx.x * blockDim.x + threadIdx.x;
    if (idx >= Bc * Dc) return;
    int b = idx / Dc, j = idx % Dc;
    cls[idx] = t[((long long)b * Sc) * Dc + j];
}

// ---------------- host helpers ----------------
static void run_hgemm(const __half* A, const __half* Bm, const float* bias,
                      const float* res, float* Cf, __half* C2, int M, int N, int K,
                      int ldc, int act) {
    dim3 grid((N + 127) / 128, (M + 127) / 128, 1);
    hgemm_kernel<<<grid, 256, GEMM_SMEM>>>(A, Bm, bias, res, Cf, C2, M, N, K, ldc, act);
}

extern "C" void kernel_launch(void* const* d_in, const int* in_sizes, int n_in,
                              void* d_out, int out_size) {
    const float* x       = (const float*)d_in[0];
    const float* conv_w  = (const float*)d_in[1];
    const float* conv_b  = (const float*)d_in[2];
    const float* cls_tok = (const float*)d_in[3];
    const float* pos_emb = (const float*)d_in[4];
    const float* ln1_g   = (const float*)d_in[5];
    const float* ln1_b   = (const float*)d_in[6];
    const float* wqkv    = (const float*)d_in[7];
    const float* bqkv    = (const float*)d_in[8];
    const float* wmsa    = (const float*)d_in[9];
    const float* bmsa    = (const float*)d_in[10];
    const float* ln2_g   = (const float*)d_in[11];
    const float* ln2_b   = (const float*)d_in[12];
    const float* lnm_g   = (const float*)d_in[13];
    const float* lnm_b   = (const float*)d_in[14];
    const float* w1      = (const float*)d_in[15];
    const float* b1      = (const float*)d_in[16];
    const float* w2      = (const float*)d_in[17];
    const float* b2      = (const float*)d_in[18];
    const float* lnf_g   = (const float*)d_in[19];
    const float* lnf_b   = (const float*)d_in[20];
    const float* whead   = (const float*)d_in[21];
    const float* bhead   = (const float*)d_in[22];
    float* out = (float*)d_out;

    float *t_, *h_, *cls_;
    __half *h2_, *om2_, *mb2_, *qkv2_, *col2_, *cls2_, *wq2_, *cw2_, *wm2_, *w12_, *w22_, *wh2_;
    cudaGetSymbolAddress((void**)&t_,  g_t);
    cudaGetSymbolAddress((void**)&h_,  g_h);
    cudaGetSymbolAddress((void**)&cls_, g_cls);
    cudaGetSymbolAddress((void**)&h2_, g_h2);
    cudaGetSymbolAddress((void**)&om2_, g_om2);
    cudaGetSymbolAddress((void**)&mb2_, g_mb2);
    cudaGetSymbolAddress((void**)&qkv2_, g_qkv2);
    cudaGetSymbolAddress((void**)&col2_, g_col2);
    cudaGetSymbolAddress((void**)&cls2_, g_cls2);
    cudaGetSymbolAddress((void**)&wq2_, g_wq2);
    cudaGetSymbolAddress((void**)&cw2_, g_cw2);
    cudaGetSymbolAddress((void**)&wm2_, g_wm2);
    cudaGetSymbolAddress((void**)&w12_, g_w12);
    cudaGetSymbolAddress((void**)&w22_, g_w22);
    cudaGetSymbolAddress((void**)&wh2_, g_wh2);

    cudaFuncSetAttribute(flash_kernel, cudaFuncAttributeMaxDynamicSharedMemorySize, FLASH_SMEM);
    cudaFuncSetAttribute(hgemm_kernel, cudaFuncAttributeMaxDynamicSharedMemorySize, GEMM_SMEM);

    // --- weight prep: fp16, transposed to [N][K] ---
    hcopy_kernel<<<(Dc * Dc + 255) / 256, 256>>>(conv_w, cw2_, (long long)Dc * Dc);
    {
        long long tot = (long long)Lc * 3 * Dc * Dc;
        transpose_wqkv_kernel<<<(int)((tot + 255) / 256), 256>>>(wqkv, wq2_);
    }
    {
        dim3 tb(32, 8);
        btrans_h_kernel<<<dim3(Dc / 32, Dc / 32, Lc), tb>>>(wmsa, wm2_, Dc, Dc);
        btrans_h_kernel<<<dim3(Mc / 32, Dc / 32, Lc), tb>>>(w1, w12_, Dc, Mc);
        btrans_h_kernel<<<dim3(Dc / 32, Mc / 32, Lc), tb>>>(w2, w22_, Mc, Dc);
        btrans_h_kernel<<<dim3((NCc + 31) / 32, Dc / 32, 1), tb>>>(whead, wh2_, Dc, NCc);
    }

    // --- patchify ---
    {
        long long tot = (long long)Bc * NP * Dc;
        im2col_kernel<<<(int)((tot + 255) / 256), 256>>>(x, col2_);
    }
    run_hgemm(col2_, cw2_, conv_b, nullptr, h_, nullptr, Bc * NP, Dc, Dc, Dc, 0);
    {
        long long tot = (long long)Bc * Sc * Dc;
        embed_kernel<<<(int)((tot + 255) / 256), 256>>>(h_, cls_tok, pos_emb, t_);
    }

    // --- encoder layers ---
    for (int l = 0; l < Lc; l++) {
        layernorm_kernel<<<BS, 256>>>(t_, ln1_g + l * Dc, ln1_b + l * Dc, h_, h2_, BS);
        // qkv fp16 only
        run_hgemm(h2_, wq2_ + (long long)l * 3 * Dc * Dc, bqkv + l * 3 * Dc, nullptr,
                  nullptr, qkv2_, BS, 3 * Dc, Dc, 3 * Dc, 0);
        flash_kernel<<<dim3((Sc + 127) / 128, Hc, Bc), 256, FLASH_SMEM>>>(qkv2_, om2_);
        run_hgemm(om2_, wm2_ + (long long)l * Dc * Dc, bmsa + l * Dc, h_,
                  t_, nullptr, BS, Dc, Dc, Dc, 0);
        layernorm2_kernel<<<BS, 256>>>(t_, ln2_g + l * Dc, ln2_b + l * Dc,
                                       lnm_g + l * Dc, lnm_b + l * Dc, h2_, BS);
        run_hgemm(h2_, w12_ + (long long)l * Mc * Dc, b1 + l * Mc, nullptr,
                  nullptr, mb2_, BS, Mc, Dc, Mc, 1);
        run_hgemm(mb2_, w22_ + (long long)l * Dc * Mc, b2 + l * Dc, t_,
                  t_, nullptr, BS, Dc, Mc, Dc, 0);
    }

    // --- head ---
    extract_cls_kernel<<<(Bc * Dc + 255) / 256, 256>>>(t_, cls_);
    layernorm_kernel<<<Bc, 256>>>(cls_, lnf_g, lnf_b, nullptr, cls2_, Bc);
    run_hgemm(cls2_, wh2_, bhead, nullptr, out, nullptr, Bc, NCc, Dc, NCc, 0);
    softmax_kernel<<<Bc, 256>>>(out, Bc, NCc);
}